// round 11
// baseline (speedup 1.0000x reference)
#include <cuda_runtime.h>
#include <cuda_fp16.h>
#include <cuda_bf16.h>
#include <math.h>
#include <stdint.h>

#define D_   1024
#define H_   16
#define V_   50257
#define L_   4
#define B_   2
#define S_   1024
#define DK_  64
#define DFF_ 4096
#define NTOK (B_ * S_)
#define NEGF (-3.402823466e38f)

// ---------------------------------------------------------------------------
// Device scratch
// ---------------------------------------------------------------------------
__device__ float  g_x [NTOK * D_];
__device__ __half g_xr[NTOK * D_];
__device__ __half g_q [NTOK * D_];
__device__ __half g_k [NTOK * D_];
__device__ __half g_v [NTOK * D_];
__device__ __half g_y [NTOK * D_];
__device__ __half g_ln[NTOK * D_];
__device__ __half g_h1[NTOK * DFF_];
__device__ float  g_p [2 * NTOK * D_];
__device__ __half g_wqT[L_ * D_ * D_];
__device__ __half g_wkT[L_ * D_ * D_];
__device__ __half g_wvT[L_ * D_ * D_];
__device__ __half g_woT[L_ * D_ * D_];
__device__ __half g_w1T[L_ * D_ * DFF_];
__device__ __half g_w2T[L_ * DFF_ * D_];
__device__ __half g_teh[(size_t)V_ * D_];

__device__ __forceinline__ float gelu_exact(float v) {
    return 0.5f * v * (1.0f + erff(v * 0.70710678118654752440f));
}

__device__ __forceinline__ void mma_f16(float* c, const unsigned* a, const unsigned* b) {
    asm volatile(
        "mma.sync.aligned.m16n8k16.row.col.f32.f16.f16.f32 "
        "{%0,%1,%2,%3},{%4,%5,%6,%7},{%8,%9},{%0,%1,%2,%3};"
        : "+f"(c[0]), "+f"(c[1]), "+f"(c[2]), "+f"(c[3])
        : "r"(a[0]), "r"(a[1]), "r"(a[2]), "r"(a[3]), "r"(b[0]), "r"(b[1]));
}
__device__ __forceinline__ void ldsm4(unsigned* r, uint32_t addr) {
    asm volatile("ldmatrix.sync.aligned.m8n8.x4.shared.b16 {%0,%1,%2,%3}, [%4];"
        : "=r"(r[0]), "=r"(r[1]), "=r"(r[2]), "=r"(r[3]) : "r"(addr));
}
__device__ __forceinline__ void cp16(void* s, const void* g, bool pred) {
    unsigned sa = (unsigned)__cvta_generic_to_shared(s);
    int sz = pred ? 16 : 0;
    asm volatile("cp.async.cg.shared.global [%0], [%1], 16, %2;\n"
                 :: "r"(sa), "l"(g), "r"(sz));
}
__device__ __forceinline__ void cp_commit() {
    asm volatile("cp.async.commit_group;\n" ::: "memory");
}

// ---------------------------------------------------------------------------
// Prepass
// ---------------------------------------------------------------------------
__global__ void transpose_cvt(const float* __restrict__ in, __half* __restrict__ outp,
                              int K, int N) {
    __shared__ float t[32][33];
    long long zoff = (long long)blockIdx.z * K * N;
    in += zoff; outp += zoff;
    int k0 = blockIdx.y * 32, n0 = blockIdx.x * 32;
    int tx = threadIdx.x, ty = threadIdx.y;
    #pragma unroll
    for (int i = 0; i < 4; i++)
        t[ty + i * 8][tx] = in[(long long)(k0 + ty + i * 8) * N + n0 + tx];
    __syncthreads();
    #pragma unroll
    for (int i = 0; i < 4; i++)
        outp[(long long)(n0 + ty + i * 8) * K + k0 + tx] = __float2half(t[tx][ty + i * 8]);
}

__global__ void cvt_f16_kernel(const float* __restrict__ in, __half* __restrict__ outp,
                               long long NTOTAL) {
    long long i = ((long long)blockIdx.x * 256 + threadIdx.x) * 8;
    if (i + 8 <= NTOTAL) {
        float4 v0 = *(const float4*)(in + i);
        float4 v1 = *(const float4*)(in + i + 4);
        __half2 h0 = __floats2half2_rn(v0.x, v0.y);
        __half2 h1 = __floats2half2_rn(v0.z, v0.w);
        __half2 h2 = __floats2half2_rn(v1.x, v1.y);
        __half2 h3 = __floats2half2_rn(v1.z, v1.w);
        uint4 pk;
        pk.x = *(unsigned*)&h0; pk.y = *(unsigned*)&h1;
        pk.z = *(unsigned*)&h2; pk.w = *(unsigned*)&h3;
        *(uint4*)(outp + i) = pk;
    } else {
        for (long long e = i; e < NTOTAL; e++) outp[e] = __float2half(in[e]);
    }
}

// ---------------------------------------------------------------------------
// Embedding
// ---------------------------------------------------------------------------
__global__ void embed_kernel(const int* __restrict__ idx,
                             const float* __restrict__ te,
                             const float* __restrict__ pe,
                             float* __restrict__ x, __half* __restrict__ xr) {
    int row = blockIdx.x;
    int s   = row % S_;
    int tok = idx[row];
    int c   = threadIdx.x * 4;
    float4 t = *(const float4*)(te + (size_t)tok * D_ + c);
    float4 p = *(const float4*)(pe + (size_t)s   * D_ + c);
    float4 o = make_float4(t.x + p.x, t.y + p.y, t.z + p.z, t.w + p.w);
    *(float4*)(x + (size_t)row * D_ + c) = o;
    __half* xp = xr + (size_t)row * D_ + c;
    *(__half2*)(xp)     = __floats2half2_rn(o.x, o.y);
    *(__half2*)(xp + 2) = __floats2half2_rn(o.z, o.w);
}

// ---------------------------------------------------------------------------
// Fused flash attention (unchanged)
// ---------------------------------------------------------------------------
__global__ void __launch_bounds__(256, 2)
flash_attn(const __half* __restrict__ q, const __half* __restrict__ k,
           const __half* __restrict__ v, __half* __restrict__ y)
{
    __shared__ unsigned Ksu[64 * 36];
    __shared__ __half   Vsh[64 * 72];
    unsigned* Vsu = (unsigned*)Vsh;

    const int xmap[8] = {0, 7, 1, 6, 2, 5, 3, 4};
    const int m0  = xmap[blockIdx.x] * 128;
    const int bh  = blockIdx.y;
    const int b   = bh >> 4, h = bh & 15;
    const int tid = threadIdx.x;
    const int wid = tid >> 5, lane = tid & 31;
    const int g   = lane >> 2, tq = lane & 3;
    const int r0 = m0 + wid * 16 + g;
    const int r8 = r0 + 8;
    const int RS = H_ * DK_;

    unsigned qf[4][4];
    {
        const unsigned* q0u = (const unsigned*)(q + (size_t)(b * S_ + r0) * RS + h * DK_);
        const unsigned* q8u = q0u + 8 * (RS / 2);
        const __half2 sc = __float2half2_rn(0.125f);
        #pragma unroll
        for (int s = 0; s < 4; s++) {
            __half2 a0 = __hmul2(*(const __half2*)&q0u[s * 8 + tq], sc);
            __half2 a1 = __hmul2(*(const __half2*)&q8u[s * 8 + tq], sc);
            __half2 a2 = __hmul2(*(const __half2*)&q0u[s * 8 + tq + 4], sc);
            __half2 a3 = __hmul2(*(const __half2*)&q8u[s * 8 + tq + 4], sc);
            qf[s][0] = *(unsigned*)&a0; qf[s][1] = *(unsigned*)&a1;
            qf[s][2] = *(unsigned*)&a2; qf[s][3] = *(unsigned*)&a3;
        }
    }

    float o[8][4];
    #pragma unroll
    for (int j = 0; j < 8; j++)
        #pragma unroll
        for (int c = 0; c < 4; c++) o[j][c] = 0.0f;
    float mg = NEGF, m8 = NEGF, lg = 0.0f, l8 = 0.0f;

    const int ntiles = m0 / 64 + 2;

    for (int jt = 0; jt < ntiles; jt++) {
        const int t0 = jt * 64;
        {
            #pragma unroll
            for (int i = 0; i < 2; i++) {
                int c = tid + i * 256;
                int row = c >> 3, ch = c & 7;
                uint4 kv = *(const uint4*)(k + (size_t)(b * S_ + t0 + row) * RS
                                           + h * DK_ + ch * 8);
                *(uint4*)&Ksu[row * 36 + ch * 4] = kv;
            }
            int t = tid >> 2;
            int dc = (tid & 3) * 16;
            const __half* vsrc = v + (size_t)(b * S_ + t0 + t) * RS + h * DK_ + dc;
            uint4 v0 = *(const uint4*)(vsrc);
            uint4 v1 = *(const uint4*)(vsrc + 8);
            const __half* vh0 = (const __half*)&v0;
            const __half* vh1 = (const __half*)&v1;
            #pragma unroll
            for (int i = 0; i < 8; i++) {
                Vsh[(dc + i) * 72 + t]     = vh0[i];
                Vsh[(dc + 8 + i) * 72 + t] = vh1[i];
            }
        }
        __syncthreads();

        float s[8][4];
        #pragma unroll
        for (int j = 0; j < 8; j++)
            #pragma unroll
            for (int c = 0; c < 4; c++) s[j][c] = 0.0f;

        #pragma unroll
        for (int ks = 0; ks < 4; ks++) {
            #pragma unroll
            for (int jn = 0; jn < 8; jn++) {
                unsigned bf[2];
                bf[0] = Ksu[(8 * jn + g) * 36 + 8 * ks + tq];
                bf[1] = Ksu[(8 * jn + g) * 36 + 8 * ks + tq + 4];
                mma_f16(s[jn], qf[ks], bf);
            }
        }

        if (t0 + 63 > m0) {
            #pragma unroll
            for (int jn = 0; jn < 8; jn++) {
                int c0 = t0 + 8 * jn + 2 * tq;
                if (c0     > r0) s[jn][0] = NEGF;
                if (c0 + 1 > r0) s[jn][1] = NEGF;
                if (c0     > r8) s[jn][2] = NEGF;
                if (c0 + 1 > r8) s[jn][3] = NEGF;
            }
        }

        float tmg = NEGF, tm8 = NEGF;
        #pragma unroll
        for (int jn = 0; jn < 8; jn++) {
            tmg = fmaxf(tmg, fmaxf(s[jn][0], s[jn][1]));
            tm8 = fmaxf(tm8, fmaxf(s[jn][2], s[jn][3]));
        }
        tmg = fmaxf(tmg, __shfl_xor_sync(0xffffffffu, tmg, 1));
        tmg = fmaxf(tmg, __shfl_xor_sync(0xffffffffu, tmg, 2));
        tm8 = fmaxf(tm8, __shfl_xor_sync(0xffffffffu, tm8, 1));
        tm8 = fmaxf(tm8, __shfl_xor_sync(0xffffffffu, tm8, 2));

        float mgn = fmaxf(mg, tmg), m8n = fmaxf(m8, tm8);
        float ag = expf(mg - mgn), a8 = expf(m8 - m8n);

        float rsg = 0.0f, rs8 = 0.0f;
        #pragma unroll
        for (int jn = 0; jn < 8; jn++) {
            s[jn][0] = expf(s[jn][0] - mgn);
            s[jn][1] = expf(s[jn][1] - mgn);
            s[jn][2] = expf(s[jn][2] - m8n);
            s[jn][3] = expf(s[jn][3] - m8n);
            rsg += s[jn][0] + s[jn][1];
            rs8 += s[jn][2] + s[jn][3];
        }
        rsg += __shfl_xor_sync(0xffffffffu, rsg, 1);
        rsg += __shfl_xor_sync(0xffffffffu, rsg, 2);
        rs8 += __shfl_xor_sync(0xffffffffu, rs8, 1);
        rs8 += __shfl_xor_sync(0xffffffffu, rs8, 2);

        lg = lg * ag + rsg;
        l8 = l8 * a8 + rs8;
        mg = mgn; m8 = m8n;

        #pragma unroll
        for (int jd = 0; jd < 8; jd++) {
            o[jd][0] *= ag; o[jd][1] *= ag;
            o[jd][2] *= a8; o[jd][3] *= a8;
        }

        #pragma unroll
        for (int u = 0; u < 4; u++) {
            unsigned af[4];
            __half2 p0 = __floats2half2_rn(s[2 * u][0], s[2 * u][1]);
            __half2 p1 = __floats2half2_rn(s[2 * u][2], s[2 * u][3]);
            __half2 p2 = __floats2half2_rn(s[2 * u + 1][0], s[2 * u + 1][1]);
            __half2 p3 = __floats2half2_rn(s[2 * u + 1][2], s[2 * u + 1][3]);
            af[0] = *(unsigned*)&p0; af[1] = *(unsigned*)&p1;
            af[2] = *(unsigned*)&p2; af[3] = *(unsigned*)&p3;
            #pragma unroll
            for (int jd = 0; jd < 8; jd++) {
                unsigned bf[2];
                bf[0] = Vsu[(8 * jd + g) * 36 + 8 * u + tq];
                bf[1] = Vsu[(8 * jd + g) * 36 + 8 * u + tq + 4];
                mma_f16(o[jd], af, bf);
            }
        }
        __syncthreads();
    }

    float ig = 1.0f / lg, i8 = 1.0f / l8;
    __half* y0 = y + (size_t)(b * S_ + r0) * RS + h * DK_;
    __half* y8 = y0 + 8 * RS;
    #pragma unroll
    for (int jd = 0; jd < 8; jd++) {
        *(__half2*)(y0 + 8 * jd + 2 * tq) =
            __floats2half2_rn(o[jd][0] * ig, o[jd][1] * ig);
        *(__half2*)(y8 + 8 * jd + 2 * tq) =
            __floats2half2_rn(o[jd][2] * i8, o[jd][3] * i8);
    }
}

// ---------------------------------------------------------------------------
// FP16 MMA GEMM (narrow, 128x128, 256 thr) — QKV + split-K
// ---------------------------------------------------------------------------
template <typename CT, bool GELU_ACT, bool QKV, int SPLITK, bool NGUARD>
__global__ void __launch_bounds__(256, 2)
mma_gemm(const __half* __restrict__ Ag, const __half* __restrict__ Bg,
         const float* __restrict__ biasg, CT* __restrict__ Cg,
         int M, int N, int K, int lda, int ldb, int ldc,
         const __half* Bg2, const float* bias2, CT* Cg2,
         const __half* Bg3, const float* bias3, CT* Cg3)
{
    constexpr int BM = 128, BK = 32, STAGES = 4;
    constexpr int STR = 20;
    constexpr int TSZ = BM * STR;

    extern __shared__ unsigned smem_u[];
    unsigned* AsB = smem_u;
    unsigned* BsB = smem_u + STAGES * TSZ;

    const int tid  = threadIdx.x;
    const int wid  = tid >> 5;
    const int lane = tid & 31;
    const int g    = lane >> 2;
    const int tq   = lane & 3;
    const int m0   = NGUARD ? blockIdx.x * BM : blockIdx.y * BM;
    const int n0   = NGUARD ? blockIdx.y * BM : blockIdx.x * BM;
    const int z    = blockIdx.z;

    const __half* A = Ag;
    const __half* B = Bg;
    const float* bias = biasg;
    CT* C = Cg;

    if (QKV) {
        if (z == 1) { B = Bg2; bias = bias2; C = Cg2; }
        else if (z == 2) { B = Bg3; bias = bias3; C = Cg3; }
    } else if (SPLITK > 1) {
        C = Cg + (long long)z * M * ldc;
    }

    const int rowbase = (wid & 3) * 32;
    const int colbase = (wid >> 2) * 64;

    float acc[2][8][4];
    #pragma unroll
    for (int i = 0; i < 2; i++)
        #pragma unroll
        for (int j = 0; j < 8; j++)
            #pragma unroll
            for (int qq = 0; qq < 4; qq++) acc[i][j][qq] = 0.0f;

    int kbeg = 0, kend = K;
    if (SPLITK > 1) { kbeg = z * (K / SPLITK); kend = kbeg + K / SPLITK; }
    const int ntiles = (kend - kbeg) / BK;

    auto issue_stage = [&](int stage, int k0) {
        unsigned* as = AsB + stage * TSZ;
        unsigned* bs = BsB + stage * TSZ;
        #pragma unroll
        for (int i = 0; i < 2; i++) {
            int c = tid + i * 256;
            int row = c >> 2, ch = c & 3;
            cp16(&as[row * STR + ch * 4],
                 A + (long long)(m0 + row) * lda + k0 + ch * 8, true);
        }
        #pragma unroll
        for (int i = 0; i < 2; i++) {
            int c = tid + i * 256;
            int row = c >> 2, ch = c & 3;
            bool ok = !NGUARD || (n0 + row) < N;
            cp16(&bs[row * STR + ch * 4],
                 B + (long long)(n0 + row) * ldb + k0 + ch * 8, ok);
        }
        cp_commit();
    };

    const int lrow  = (lane & 7) + ((lane >> 3) & 1) * 8;
    const int lkoff = ((lane >> 4) & 1) * 16;
    const uint32_t offA = (uint32_t)((rowbase + lrow) * 80 + lkoff);
    const uint32_t offB = (uint32_t)((colbase + lrow) * 80 + lkoff);
    const uint32_t smemA = (uint32_t)__cvta_generic_to_shared(AsB);
    const uint32_t smemB = (uint32_t)__cvta_generic_to_shared(BsB);

    issue_stage(0, kbeg);
    if (ntiles > 1) issue_stage(1, kbeg + BK);
    if (ntiles > 2) issue_stage(2, kbeg + 2 * BK);

    for (int t = 0; t < ntiles; t++) {
        int rem = ntiles - 1 - t;
        if (rem >= 2)
            asm volatile("cp.async.wait_group 2;\n" ::: "memory");
        else if (rem == 1)
            asm volatile("cp.async.wait_group 1;\n" ::: "memory");
        else
            asm volatile("cp.async.wait_group 0;\n" ::: "memory");
        __syncthreads();

        if (t + 3 < ntiles) issue_stage((t + 3) % STAGES, kbeg + (t + 3) * BK);

        const uint32_t aBase = smemA + (uint32_t)((t % STAGES) * TSZ * 4) + offA;
        const uint32_t bBase = smemB + (uint32_t)((t % STAGES) * TSZ * 4) + offB;

        #pragma unroll
        for (int ks2 = 0; ks2 < 2; ks2++) {
            const uint32_t ko = ks2 * 32;
            unsigned af[2][4];
            ldsm4(af[0], aBase + ko);
            ldsm4(af[1], aBase + ko + 1280);
            unsigned bf[8][2];
            #pragma unroll
            for (int p = 0; p < 4; p++) {
                unsigned tmp[4];
                ldsm4(tmp, bBase + ko + p * 1280);
                bf[2 * p][0]     = tmp[0];
                bf[2 * p + 1][0] = tmp[1];
                bf[2 * p][1]     = tmp[2];
                bf[2 * p + 1][1] = tmp[3];
            }
            #pragma unroll
            for (int i = 0; i < 2; i++)
                #pragma unroll
                for (int j = 0; j < 8; j++)
                    mma_f16(acc[i][j], af[i], bf[j]);
        }
    }

    #pragma unroll
    for (int i = 0; i < 2; i++) {
        #pragma unroll
        for (int j = 0; j < 8; j++) {
            int r = m0 + rowbase + i * 16 + g;
            int c = n0 + colbase + j * 8 + tq * 2;
            #pragma unroll
            for (int hh = 0; hh < 2; hh++) {
                int rr = r + hh * 8;
                float v0 = acc[i][j][hh * 2 + 0];
                float v1 = acc[i][j][hh * 2 + 1];
                if constexpr (SPLITK > 1) {
                    *(float2*)((float*)C + (long long)rr * ldc + c) = make_float2(v0, v1);
                } else {
                    if (bias) { v0 += bias[c]; v1 += bias[c + 1]; }
                    if (GELU_ACT) { v0 = gelu_exact(v0); v1 = gelu_exact(v1); }
                    if constexpr (NGUARD) {
                        float* Cf = (float*)C;
                        if (c < N)     Cf[(long long)rr * ldc + c]     = v0;
                        if (c + 1 < N) Cf[(long long)rr * ldc + c + 1] = v1;
                    } else if constexpr (sizeof(CT) == 2) {
                        *(__half2*)((__half*)C + (long long)rr * ldc + c) =
                            __floats2half2_rn(v0, v1);
                    } else {
                        *(float2*)((float*)C + (long long)rr * ldc + c) =
                            make_float2(v0, v1);
                    }
                }
            }
        }
    }
}

// ---------------------------------------------------------------------------
// FP16 MMA GEMM (big, 256x128 block, 64x64 warp tile, 256 thr) — W1 + logits.
// 1.5x higher FLOP/smem-byte than the 32x64 warp tile. Grid: m on blockIdx.x.
// ---------------------------------------------------------------------------
template <typename CT, bool GELU_ACT, bool NGUARD>
__global__ void __launch_bounds__(256, 1)
mma_gemm_big(const __half* __restrict__ A, const __half* __restrict__ B,
             const float* __restrict__ bias, CT* __restrict__ C,
             int M, int N, int K, int lda, int ldb, int ldc)
{
    constexpr int BM = 256, BN = 128, BK = 32, STAGES = 4;
    constexpr int STR = 20;                 // half2 units per row (80 B)
    constexpr int ASZ = BM * STR;
    constexpr int BSZ = BN * STR;

    extern __shared__ unsigned smem_u[];
    unsigned* AsB = smem_u;
    unsigned* BsB = smem_u + STAGES * ASZ;

    const int tid  = threadIdx.x;
    const int wid  = tid >> 5;
    const int lane = tid & 31;
    const int g    = lane >> 2;
    const int tq   = lane & 3;
    const int m0   = blockIdx.x * BM;
    const int n0   = blockIdx.y * BN;

    const int rowbase = (wid & 3) * 64;     // 4 m-warps x 64
    const int colbase = (wid >> 2) * 64;    // 2 n-warps x 64

    float acc[4][8][4];
    #pragma unroll
    for (int i = 0; i < 4; i++)
        #pragma unroll
        for (int j = 0; j < 8; j++)
            #pragma unroll
            for (int qq = 0; qq < 4; qq++) acc[i][j][qq] = 0.0f;

    const int ntiles = K / BK;

    auto issue_stage = [&](int stage, int k0) {
        unsigned* as = AsB + stage * ASZ;
        unsigned* bs = BsB + stage * BSZ;
        #pragma unroll
        for (int i = 0; i < 4; i++) {       // A: 1024 chunks = 256 rows x 4
            int c = tid + i * 256;
            int row = c >> 2, ch = c & 3;
            cp16(&as[row * STR + ch * 4],
                 A + (long long)(m0 + row) * lda + k0 + ch * 8, true);
        }
        #pragma unroll
        for (int i = 0; i < 2; i++) {       // B: 512 chunks = 128 rows x 4
            int c = tid + i * 256;
            int row = c >> 2, ch = c & 3;
            bool ok = !NGUARD || (n0 + row) < N;
            cp16(&bs[row * STR + ch * 4],
                 B + (long long)(n0 + row) * ldb + k0 + ch * 8, ok);
        }
        cp_commit();
    };

    const int lrow  = (lane & 7) + ((lane >> 3) & 1) * 8;
    const int lkoff = ((lane >> 4) & 1) * 16;
    const uint32_t offA = (uint32_t)((rowbase + lrow) * 80 + lkoff);
    const uint32_t offB = (uint32_t)((colbase + lrow) * 80 + lkoff);
    const uint32_t smemA = (uint32_t)__cvta_generic_to_shared(AsB);
    const uint32_t smemB = (uint32_t)__cvta_generic_to_shared(BsB);

    issue_stage(0, 0);
    if (ntiles > 1) issue_stage(1, BK);
    if (ntiles > 2) issue_stage(2, 2 * BK);

    for (int t = 0; t < ntiles; t++) {
        int rem = ntiles - 1 - t;
        if (rem >= 2)
            asm volatile("cp.async.wait_group 2;\n" ::: "memory");
        else if (rem == 1)
            asm volatile("cp.async.wait_group 1;\n" ::: "memory");
        else
            asm volatile("cp.async.wait_group 0;\n" ::: "memory");
        __syncthreads();

        if (t + 3 < ntiles) issue_stage((t + 3) % STAGES, (t + 3) * BK);

        const uint32_t aBase = smemA + (uint32_t)((t % STAGES) * ASZ * 4) + offA;
        const uint32_t bBase = smemB + (uint32_t)((t % STAGES) * BSZ * 4) + offB;

        #pragma unroll
        for (int ks2 = 0; ks2 < 2; ks2++) {
            const uint32_t ko = ks2 * 32;
            unsigned af[4][4];
            #pragma unroll
            for (int i = 0; i < 4; i++)
                ldsm4(af[i], aBase + ko + i * 1280);   // 16 rows apart
            unsigned bf[8][2];
            #pragma unroll
            for (int p = 0; p < 4; p++) {
                unsigned tmp[4];
                ldsm4(tmp, bBase + ko + p * 1280);
                bf[2 * p][0]     = tmp[0];
                bf[2 * p + 1][0] = tmp[1];
                bf[2 * p][1]     = tmp[2];
                bf[2 * p + 1][1] = tmp[3];
            }
            #pragma unroll
            for (int i = 0; i < 4; i++)
                #pragma unroll
                for (int j = 0; j < 8; j++)
                    mma_f16(acc[i][j], af[i], bf[j]);
        }
    }

    #pragma unroll
    for (int i = 0; i < 4; i++) {
        #pragma unroll
        for (int j = 0; j < 8; j++) {
            int r = m0 + rowbase + i * 16 + g;
            int c = n0 + colbase + j * 8 + tq * 2;
            #pragma unroll
            for (int hh = 0; hh < 2; hh++) {
                int rr = r + hh * 8;
                float v0 = acc[i][j][hh * 2 + 0];
                float v1 = acc[i][j][hh * 2 + 1];
                if (bias) { v0 += bias[c]; v1 += bias[c + 1]; }
                if (GELU_ACT) { v0 = gelu_exact(v0); v1 = gelu_exact(v1); }
                if constexpr (NGUARD) {
                    float* Cf = (float*)C;
                    if (c < N)     Cf[(long long)rr * ldc + c]     = v0;
                    if (c + 1 < N) Cf[(long long)rr * ldc + c + 1] = v1;
                } else if constexpr (sizeof(CT) == 2) {
                    *(__half2*)((__half*)C + (long long)rr * ldc + c) =
                        __floats2half2_rn(v0, v1);
                } else {
                    *(float2*)((float*)C + (long long)rr * ldc + c) =
                        make_float2(v0, v1);
                }
            }
        }
    }
}

// ---------------------------------------------------------------------------
// Split-K reduce (plain) and fused reduce+LayerNorm
// ---------------------------------------------------------------------------
__global__ void reduce_splitk(const float* __restrict__ part,
                              const float* __restrict__ bias,
                              float* __restrict__ x, __half* __restrict__ xr,
                              int NN, int ldc) {
    int idx = (blockIdx.x * 256 + threadIdx.x) * 4;
    float4 p0 = *(const float4*)(part + idx);
    float4 p1 = *(const float4*)(part + idx + NN);
    float4 xv = *(const float4*)(x + idx);
    float4 bv = *(const float4*)(bias + (idx % ldc));
    float4 o;
    o.x = xv.x + p0.x + p1.x + bv.x;
    o.y = xv.y + p0.y + p1.y + bv.y;
    o.z = xv.z + p0.z + p1.z + bv.z;
    o.w = xv.w + p0.w + p1.w + bv.w;
    *(float4*)(x + idx) = o;
    *(__half2*)(xr + idx)     = __floats2half2_rn(o.x, o.y);
    *(__half2*)(xr + idx + 2) = __floats2half2_rn(o.z, o.w);
}

__global__ void reduce_ln_kernel(const float* __restrict__ part,
                                 const float* __restrict__ bias,
                                 float* __restrict__ x, __half* __restrict__ xr,
                                 const float* __restrict__ g,
                                 const float* __restrict__ bb,
                                 __half* __restrict__ lnout, int NN) {
    const int row = blockIdx.x;
    const int tid = threadIdx.x;
    const int idx = row * D_ + tid * 4;
    __shared__ float rs[256];
    __shared__ float rq[256];

    float4 p0 = *(const float4*)(part + idx);
    float4 p1 = *(const float4*)(part + idx + NN);
    float4 xv = *(const float4*)(x + idx);
    float4 bv = *(const float4*)(bias + tid * 4);
    float4 o;
    o.x = xv.x + p0.x + p1.x + bv.x;
    o.y = xv.y + p0.y + p1.y + bv.y;
    o.z = xv.z + p0.z + p1.z + bv.z;
    o.w = xv.w + p0.w + p1.w + bv.w;
    *(float4*)(x + idx) = o;
    *(__half2*)(xr + idx)     = __floats2half2_rn(o.x, o.y);
    *(__half2*)(xr + idx + 2) = __floats2half2_rn(o.z, o.w);

    float s  = o.x + o.y + o.z + o.w;
    float sq = o.x * o.x + o.y * o.y + o.z * o.z + o.w * o.w;
    rs[tid] = s; rq[tid] = sq;
    __syncthreads();
    for (int off = 128; off > 0; off >>= 1) {
        if (tid < off) { rs[tid] += rs[tid + off]; rq[tid] += rq[tid + off]; }
        __syncthreads();
    }
    float mu  = rs[0] * (1.0f / D_);
    float var = rq[0] * (1.0f / D_) - mu * mu;
    float rstd = rsqrtf(var + 1e-5f);

    int c = tid * 4;
    float4 gv = *(const float4*)(g + c);
    float4 bv2 = *(const float4*)(bb + c);
    float o0 = (o.x - mu) * rstd * gv.x + bv2.x;
    float o1 = (o.y - mu) * rstd * gv.y + bv2.y;
    float o2 = (o.z - mu) * rstd * gv.z + bv2.z;
    float o3 = (o.w - mu) * rstd * gv.w + bv2.w;
    __half* op = lnout + (size_t)row * D_ + c;
    *(__half2*)(op)     = __floats2half2_rn(o0, o1);
    *(__half2*)(op + 2) = __floats2half2_rn(o2, o3);
}

// ---------------------------------------------------------------------------
// Host launcher — dual-stream prepass overlap + big-tile W1/logits
// ---------------------------------------------------------------------------
extern "C" void kernel_launch(void* const* d_in, const int* in_sizes, int n_in,
                              void* d_out, int out_size) {
    const int*   idx   = (const int*)  d_in[0];
    const float* te    = (const float*)d_in[1];
    const float* pe    = (const float*)d_in[2];
    const float* wq    = (const float*)d_in[3];
    const float* bq    = (const float*)d_in[4];
    const float* wk    = (const float*)d_in[5];
    const float* bk    = (const float*)d_in[6];
    const float* wv    = (const float*)d_in[7];
    const float* bv    = (const float*)d_in[8];
    const float* wo    = (const float*)d_in[9];
    const float* bo    = (const float*)d_in[10];
    const float* ln2g  = (const float*)d_in[11];
    const float* ln2b  = (const float*)d_in[12];
    const float* w1    = (const float*)d_in[13];
    const float* b1    = (const float*)d_in[14];
    const float* w2    = (const float*)d_in[15];
    const float* b2    = (const float*)d_in[16];
    const float* lnfg  = (const float*)d_in[17];
    const float* lnfb  = (const float*)d_in[18];
    float* out = (float*)d_out;

    float *x, *p;
    __half *xr, *q, *k, *v, *y, *ln, *h1;
    __half *wqT, *wkT, *wvT, *woT, *w1T, *w2T, *teh;
    cudaGetSymbolAddress((void**)&x,  g_x);
    cudaGetSymbolAddress((void**)&xr, g_xr);
    cudaGetSymbolAddress((void**)&q,  g_q);
    cudaGetSymbolAddress((void**)&k,  g_k);
    cudaGetSymbolAddress((void**)&v,  g_v);
    cudaGetSymbolAddress((void**)&y,  g_y);
    cudaGetSymbolAddress((void**)&ln, g_ln);
    cudaGetSymbolAddress((void**)&h1, g_h1);
    cudaGetSymbolAddress((void**)&p,  g_p);
    cudaGetSymbolAddress((void**)&wqT, g_wqT);
    cudaGetSymbolAddress((void**)&wkT, g_wkT);
    cudaGetSymbolAddress((void**)&wvT, g_wvT);
    cudaGetSymbolAddress((void**)&woT, g_woT);
    cudaGetSymbolAddress((void**)&w1T, g_w1T);
    cudaGetSymbolAddress((void**)&w2T, g_w2T);
    cudaGetSymbolAddress((void**)&teh, g_teh);

    const size_t smem_nar = 4 * 2 * 128 * 20 * 4;               // 81920
    const size_t smem_big = 4 * (256 + 128) * 20 * 4;           // 122880

    auto kq  = mma_gemm<__half, false, true,  1, false>;
    auto ksk = mma_gemm<float,  false, false, 2, false>;
    auto kw1 = mma_gemm_big<__half, true,  false>;
    auto klg = mma_gemm_big<float,  false, true>;
    cudaFuncSetAttribute(kq,  cudaFuncAttributeMaxDynamicSharedMemorySize, (int)smem_nar);
    cudaFuncSetAttribute(ksk, cudaFuncAttributeMaxDynamicSharedMemorySize, (int)smem_nar);
    cudaFuncSetAttribute(kw1, cudaFuncAttributeMaxDynamicSharedMemorySize, (int)smem_big);
    cudaFuncSetAttribute(klg, cudaFuncAttributeMaxDynamicSharedMemorySize, (int)smem_big);

    static cudaStream_t s2 = nullptr;
    static cudaEvent_t evF = nullptr, evA = nullptr, evB = nullptr;
    if (!s2) {
        cudaStreamCreateWithFlags(&s2, cudaStreamNonBlocking);
        cudaEventCreateWithFlags(&evF, cudaEventDisableTiming);
        cudaEventCreateWithFlags(&evA, cudaEventDisableTiming);
        cudaEventCreateWithFlags(&evB, cudaEventDisableTiming);
    }

    dim3 tb(32, 8);
    cudaEventRecord(evF, 0);
    cudaStreamWaitEvent(s2, evF, 0);

    transpose_cvt<<<dim3(32, 32, 1), tb, 0, s2>>>(wq, wqT, D_, D_);
    transpose_cvt<<<dim3(32, 32, 1), tb, 0, s2>>>(wk, wkT, D_, D_);
    transpose_cvt<<<dim3(32, 32, 1), tb, 0, s2>>>(wv, wvT, D_, D_);
    transpose_cvt<<<dim3(32, 32, 1), tb, 0, s2>>>(wo, woT, D_, D_);
    transpose_cvt<<<dim3(DFF_ / 32, D_ / 32, 1), tb, 0, s2>>>(w1, w1T, D_, DFF_);
    transpose_cvt<<<dim3(D_ / 32, DFF_ / 32, 1), tb, 0, s2>>>(w2, w2T, DFF_, D_);
    cudaEventRecord(evA, s2);

    transpose_cvt<<<dim3(32, 32, L_ - 1), tb, 0, s2>>>(wq + (size_t)D_ * D_, wqT + (size_t)D_ * D_, D_, D_);
    transpose_cvt<<<dim3(32, 32, L_ - 1), tb, 0, s2>>>(wk + (size_t)D_ * D_, wkT + (size_t)D_ * D_, D_, D_);
    transpose_cvt<<<dim3(32, 32, L_ - 1), tb, 0, s2>>>(wv + (size_t)D_ * D_, wvT + (size_t)D_ * D_, D_, D_);
    transpose_cvt<<<dim3(32, 32, L_ - 1), tb, 0, s2>>>(wo + (size_t)D_ * D_, woT + (size_t)D_ * D_, D_, D_);
    transpose_cvt<<<dim3(DFF_ / 32, D_ / 32, L_ - 1), tb, 0, s2>>>(w1 + (size_t)D_ * DFF_, w1T + (size_t)D_ * DFF_, D_, DFF_);
    transpose_cvt<<<dim3(D_ / 32, DFF_ / 32, L_ - 1), tb, 0, s2>>>(w2 + (size_t)DFF_ * D_, w2T + (size_t)DFF_ * D_, DFF_, D_);
    {
        long long nte = (long long)V_ * D_;
        int gte = (int)((nte + 2047) / 2048);
        cvt_f16_kernel<<<gte, 256, 0, s2>>>(te, teh, nte);
    }
    cudaEventRecord(evB, s2);

    embed_kernel<<<NTOK, 256>>>(idx, te, pe, x, xr);

    const dim3 gQKV(D_ / 128, NTOK / 128, 3);
    const dim3 gSK (D_ / 128, NTOK / 128, 2);
    const dim3 gFB (NTOK / 256, DFF_ / 128);          // big W1: (8, 32)
    const dim3 gFA (S_ / 128, B_ * H_);
    const dim3 gLgB(NTOK / 256, (V_ + 127) / 128);    // big logits: (8, 393)
    const int NN = NTOK * D_;

    for (int l = 0; l < L_; l++) {
        if (l == 0) cudaStreamWaitEvent(0, evA, 0);
        if (l == 1) cudaStreamWaitEvent(0, evB, 0);

        const __half* wq_l = wqT + (size_t)l * D_ * D_;
        const __half* wk_l = wkT + (size_t)l * D_ * D_;
        const __half* wv_l = wvT + (size_t)l * D_ * D_;
        const __half* wo_l = woT + (size_t)l * D_ * D_;
        const __half* w1_l = w1T + (size_t)l * D_ * DFF_;
        const __half* w2_l = w2T + (size_t)l * DFF_ * D_;

        kq<<<gQKV, 256, smem_nar>>>(
            xr, wq_l, bq + l * D_, q, NTOK, D_, D_, D_, D_, D_,
            wk_l, bk + l * D_, k, wv_l, bv + l * D_, v);

        flash_attn<<<gFA, 256>>>(q, k, v, y);

        ksk<<<gSK, 256, smem_nar>>>(
            y, wo_l, nullptr, p, NTOK, D_, D_, D_, D_, D_,
            nullptr, nullptr, nullptr, nullptr, nullptr, nullptr);
        reduce_ln_kernel<<<NTOK, 256>>>(p, bo + l * D_, x, xr,
                                        ln2g + l * D_, ln2b + l * D_, ln, NN);

        kw1<<<gFB, 256, smem_big>>>(
            ln, w1_l, b1 + l * DFF_, h1, NTOK, DFF_, D_, D_, D_, DFF_);

        ksk<<<gSK, 256, smem_nar>>>(
            h1, w2_l, nullptr, p, NTOK, D_, DFF_, DFF_, DFF_, D_,
            nullptr, nullptr, nullptr, nullptr, nullptr, nullptr);
        if (l < L_ - 1) {
            reduce_splitk<<<NN / 1024, 256>>>(p, b2 + l * D_, x, xr, NN, D_);
        } else {
            reduce_ln_kernel<<<NTOK, 256>>>(p, b2 + l * D_, x, xr,
                                            lnfg, lnfb, ln, NN);
        }
    }

    // logits = lnf(x) @ te^T
    klg<<<gLgB, 256, smem_big>>>(
        ln, teh, nullptr, out, NTOK, V_, D_, D_, D_, V_);
}

// round 12
// speedup vs baseline: 1.0501x; 1.0501x over previous
#include <cuda_runtime.h>
#include <cuda_fp16.h>
#include <cuda_bf16.h>
#include <math.h>
#include <stdint.h>

#define D_   1024
#define H_   16
#define V_   50257
#define L_   4
#define B_   2
#define S_   1024
#define DK_  64
#define DFF_ 4096
#define NTOK (B_ * S_)
#define NEGF (-3.402823466e38f)

// ---------------------------------------------------------------------------
// Device scratch
// ---------------------------------------------------------------------------
__device__ float  g_x [NTOK * D_];
__device__ __half g_xr[NTOK * D_];
__device__ __half g_q [NTOK * D_];
__device__ __half g_k [NTOK * D_];
__device__ __half g_v [NTOK * D_];
__device__ __half g_y [NTOK * D_];
__device__ __half g_ln[NTOK * D_];
__device__ __half g_h1[NTOK * DFF_];
__device__ float  g_p [2 * NTOK * D_];
__device__ __half g_wqT[L_ * D_ * D_];
__device__ __half g_wkT[L_ * D_ * D_];
__device__ __half g_wvT[L_ * D_ * D_];
__device__ __half g_woT[L_ * D_ * D_];
__device__ __half g_w1T[L_ * D_ * DFF_];
__device__ __half g_w2T[L_ * DFF_ * D_];
__device__ __half g_teh[(size_t)V_ * D_];

__device__ __forceinline__ float gelu_exact(float v) {
    return 0.5f * v * (1.0f + erff(v * 0.70710678118654752440f));
}

__device__ __forceinline__ void mma_f16(float* c, const unsigned* a, const unsigned* b) {
    asm volatile(
        "mma.sync.aligned.m16n8k16.row.col.f32.f16.f16.f32 "
        "{%0,%1,%2,%3},{%4,%5,%6,%7},{%8,%9},{%0,%1,%2,%3};"
        : "+f"(c[0]), "+f"(c[1]), "+f"(c[2]), "+f"(c[3])
        : "r"(a[0]), "r"(a[1]), "r"(a[2]), "r"(a[3]), "r"(b[0]), "r"(b[1]));
}
__device__ __forceinline__ void ldsm4(unsigned* r, uint32_t addr) {
    asm volatile("ldmatrix.sync.aligned.m8n8.x4.shared.b16 {%0,%1,%2,%3}, [%4];"
        : "=r"(r[0]), "=r"(r[1]), "=r"(r[2]), "=r"(r[3]) : "r"(addr));
}
__device__ __forceinline__ void cp16(void* s, const void* g, bool pred) {
    unsigned sa = (unsigned)__cvta_generic_to_shared(s);
    int sz = pred ? 16 : 0;
    asm volatile("cp.async.cg.shared.global [%0], [%1], 16, %2;\n"
                 :: "r"(sa), "l"(g), "r"(sz));
}
__device__ __forceinline__ void cp_commit() {
    asm volatile("cp.async.commit_group;\n" ::: "memory");
}

// ---------------------------------------------------------------------------
// Prepass: transpose [K,N] fp32 -> [N,K] fp16 ; wide cast for te
// ---------------------------------------------------------------------------
__global__ void transpose_cvt(const float* __restrict__ in, __half* __restrict__ outp,
                              int K, int N) {
    __shared__ float t[32][33];
    long long zoff = (long long)blockIdx.z * K * N;
    in += zoff; outp += zoff;
    int k0 = blockIdx.y * 32, n0 = blockIdx.x * 32;
    int tx = threadIdx.x, ty = threadIdx.y;
    #pragma unroll
    for (int i = 0; i < 4; i++)
        t[ty + i * 8][tx] = in[(long long)(k0 + ty + i * 8) * N + n0 + tx];
    __syncthreads();
    #pragma unroll
    for (int i = 0; i < 4; i++)
        outp[(long long)(n0 + ty + i * 8) * K + k0 + tx] = __float2half(t[tx][ty + i * 8]);
}

__global__ void cvt_f16_kernel(const float* __restrict__ in, __half* __restrict__ outp,
                               long long NTOTAL) {
    long long i = ((long long)blockIdx.x * 256 + threadIdx.x) * 8;
    if (i + 8 <= NTOTAL) {
        float4 v0 = *(const float4*)(in + i);
        float4 v1 = *(const float4*)(in + i + 4);
        __half2 h0 = __floats2half2_rn(v0.x, v0.y);
        __half2 h1 = __floats2half2_rn(v0.z, v0.w);
        __half2 h2 = __floats2half2_rn(v1.x, v1.y);
        __half2 h3 = __floats2half2_rn(v1.z, v1.w);
        uint4 pk;
        pk.x = *(unsigned*)&h0; pk.y = *(unsigned*)&h1;
        pk.z = *(unsigned*)&h2; pk.w = *(unsigned*)&h3;
        *(uint4*)(outp + i) = pk;
    } else {
        for (long long e = i; e < NTOTAL; e++) outp[e] = __float2half(in[e]);
    }
}

// ---------------------------------------------------------------------------
// Embedding
// ---------------------------------------------------------------------------
__global__ void embed_kernel(const int* __restrict__ idx,
                             const float* __restrict__ te,
                             const float* __restrict__ pe,
                             float* __restrict__ x, __half* __restrict__ xr) {
    int row = blockIdx.x;
    int s   = row % S_;
    int tok = idx[row];
    int c   = threadIdx.x * 4;
    float4 t = *(const float4*)(te + (size_t)tok * D_ + c);
    float4 p = *(const float4*)(pe + (size_t)s   * D_ + c);
    float4 o = make_float4(t.x + p.x, t.y + p.y, t.z + p.z, t.w + p.w);
    *(float4*)(x + (size_t)row * D_ + c) = o;
    __half* xp = xr + (size_t)row * D_ + c;
    *(__half2*)(xp)     = __floats2half2_rn(o.x, o.y);
    *(__half2*)(xp + 2) = __floats2half2_rn(o.z, o.w);
}

// ---------------------------------------------------------------------------
// Fused flash attention, fp16 MMA (unchanged from R8/R9)
// ---------------------------------------------------------------------------
__global__ void __launch_bounds__(256, 2)
flash_attn(const __half* __restrict__ q, const __half* __restrict__ k,
           const __half* __restrict__ v, __half* __restrict__ y)
{
    __shared__ unsigned Ksu[64 * 36];
    __shared__ __half   Vsh[64 * 72];
    unsigned* Vsu = (unsigned*)Vsh;

    const int xmap[8] = {0, 7, 1, 6, 2, 5, 3, 4};
    const int m0  = xmap[blockIdx.x] * 128;
    const int bh  = blockIdx.y;
    const int b   = bh >> 4, h = bh & 15;
    const int tid = threadIdx.x;
    const int wid = tid >> 5, lane = tid & 31;
    const int g   = lane >> 2, tq = lane & 3;
    const int r0 = m0 + wid * 16 + g;
    const int r8 = r0 + 8;
    const int RS = H_ * DK_;

    unsigned qf[4][4];
    {
        const unsigned* q0u = (const unsigned*)(q + (size_t)(b * S_ + r0) * RS + h * DK_);
        const unsigned* q8u = q0u + 8 * (RS / 2);
        const __half2 sc = __float2half2_rn(0.125f);
        #pragma unroll
        for (int s = 0; s < 4; s++) {
            __half2 a0 = __hmul2(*(const __half2*)&q0u[s * 8 + tq], sc);
            __half2 a1 = __hmul2(*(const __half2*)&q8u[s * 8 + tq], sc);
            __half2 a2 = __hmul2(*(const __half2*)&q0u[s * 8 + tq + 4], sc);
            __half2 a3 = __hmul2(*(const __half2*)&q8u[s * 8 + tq + 4], sc);
            qf[s][0] = *(unsigned*)&a0; qf[s][1] = *(unsigned*)&a1;
            qf[s][2] = *(unsigned*)&a2; qf[s][3] = *(unsigned*)&a3;
        }
    }

    float o[8][4];
    #pragma unroll
    for (int j = 0; j < 8; j++)
        #pragma unroll
        for (int c = 0; c < 4; c++) o[j][c] = 0.0f;
    float mg = NEGF, m8 = NEGF, lg = 0.0f, l8 = 0.0f;

    const int ntiles = m0 / 64 + 2;

    for (int jt = 0; jt < ntiles; jt++) {
        const int t0 = jt * 64;
        {
            #pragma unroll
            for (int i = 0; i < 2; i++) {
                int c = tid + i * 256;
                int row = c >> 3, ch = c & 7;
                uint4 kv = *(const uint4*)(k + (size_t)(b * S_ + t0 + row) * RS
                                           + h * DK_ + ch * 8);
                *(uint4*)&Ksu[row * 36 + ch * 4] = kv;
            }
            int t = tid >> 2;
            int dc = (tid & 3) * 16;
            const __half* vsrc = v + (size_t)(b * S_ + t0 + t) * RS + h * DK_ + dc;
            uint4 v0 = *(const uint4*)(vsrc);
            uint4 v1 = *(const uint4*)(vsrc + 8);
            const __half* vh0 = (const __half*)&v0;
            const __half* vh1 = (const __half*)&v1;
            #pragma unroll
            for (int i = 0; i < 8; i++) {
                Vsh[(dc + i) * 72 + t]     = vh0[i];
                Vsh[(dc + 8 + i) * 72 + t] = vh1[i];
            }
        }
        __syncthreads();

        float s[8][4];
        #pragma unroll
        for (int j = 0; j < 8; j++)
            #pragma unroll
            for (int c = 0; c < 4; c++) s[j][c] = 0.0f;

        #pragma unroll
        for (int ks = 0; ks < 4; ks++) {
            #pragma unroll
            for (int jn = 0; jn < 8; jn++) {
                unsigned bf[2];
                bf[0] = Ksu[(8 * jn + g) * 36 + 8 * ks + tq];
                bf[1] = Ksu[(8 * jn + g) * 36 + 8 * ks + tq + 4];
                mma_f16(s[jn], qf[ks], bf);
            }
        }

        if (t0 + 63 > m0) {
            #pragma unroll
            for (int jn = 0; jn < 8; jn++) {
                int c0 = t0 + 8 * jn + 2 * tq;
                if (c0     > r0) s[jn][0] = NEGF;
                if (c0 + 1 > r0) s[jn][1] = NEGF;
                if (c0     > r8) s[jn][2] = NEGF;
                if (c0 + 1 > r8) s[jn][3] = NEGF;
            }
        }

        float tmg = NEGF, tm8 = NEGF;
        #pragma unroll
        for (int jn = 0; jn < 8; jn++) {
            tmg = fmaxf(tmg, fmaxf(s[jn][0], s[jn][1]));
            tm8 = fmaxf(tm8, fmaxf(s[jn][2], s[jn][3]));
        }
        tmg = fmaxf(tmg, __shfl_xor_sync(0xffffffffu, tmg, 1));
        tmg = fmaxf(tmg, __shfl_xor_sync(0xffffffffu, tmg, 2));
        tm8 = fmaxf(tm8, __shfl_xor_sync(0xffffffffu, tm8, 1));
        tm8 = fmaxf(tm8, __shfl_xor_sync(0xffffffffu, tm8, 2));

        float mgn = fmaxf(mg, tmg), m8n = fmaxf(m8, tm8);
        float ag = expf(mg - mgn), a8 = expf(m8 - m8n);

        float rsg = 0.0f, rs8 = 0.0f;
        #pragma unroll
        for (int jn = 0; jn < 8; jn++) {
            s[jn][0] = expf(s[jn][0] - mgn);
            s[jn][1] = expf(s[jn][1] - mgn);
            s[jn][2] = expf(s[jn][2] - m8n);
            s[jn][3] = expf(s[jn][3] - m8n);
            rsg += s[jn][0] + s[jn][1];
            rs8 += s[jn][2] + s[jn][3];
        }
        rsg += __shfl_xor_sync(0xffffffffu, rsg, 1);
        rsg += __shfl_xor_sync(0xffffffffu, rsg, 2);
        rs8 += __shfl_xor_sync(0xffffffffu, rs8, 1);
        rs8 += __shfl_xor_sync(0xffffffffu, rs8, 2);

        lg = lg * ag + rsg;
        l8 = l8 * a8 + rs8;
        mg = mgn; m8 = m8n;

        #pragma unroll
        for (int jd = 0; jd < 8; jd++) {
            o[jd][0] *= ag; o[jd][1] *= ag;
            o[jd][2] *= a8; o[jd][3] *= a8;
        }

        #pragma unroll
        for (int u = 0; u < 4; u++) {
            unsigned af[4];
            __half2 p0 = __floats2half2_rn(s[2 * u][0], s[2 * u][1]);
            __half2 p1 = __floats2half2_rn(s[2 * u][2], s[2 * u][3]);
            __half2 p2 = __floats2half2_rn(s[2 * u + 1][0], s[2 * u + 1][1]);
            __half2 p3 = __floats2half2_rn(s[2 * u + 1][2], s[2 * u + 1][3]);
            af[0] = *(unsigned*)&p0; af[1] = *(unsigned*)&p1;
            af[2] = *(unsigned*)&p2; af[3] = *(unsigned*)&p3;
            #pragma unroll
            for (int jd = 0; jd < 8; jd++) {
                unsigned bf[2];
                bf[0] = Vsu[(8 * jd + g) * 36 + 8 * u + tq];
                bf[1] = Vsu[(8 * jd + g) * 36 + 8 * u + tq + 4];
                mma_f16(o[jd], af, bf);
            }
        }
        __syncthreads();
    }

    float ig = 1.0f / lg, i8 = 1.0f / l8;
    __half* y0 = y + (size_t)(b * S_ + r0) * RS + h * DK_;
    __half* y8 = y0 + 8 * RS;
    #pragma unroll
    for (int jd = 0; jd < 8; jd++) {
        *(__half2*)(y0 + 8 * jd + 2 * tq) =
            __floats2half2_rn(o[jd][0] * ig, o[jd][1] * ig);
        *(__half2*)(y8 + 8 * jd + 2 * tq) =
            __floats2half2_rn(o[jd][2] * i8, o[jd][3] * i8);
    }
}

// ---------------------------------------------------------------------------
// FP16 MMA GEMM (narrow, 128x128, 256 thr, 4-stage, ldmatrix) — ALL GEMMs
// ---------------------------------------------------------------------------
template <typename CT, bool GELU_ACT, bool QKV, int SPLITK, bool NGUARD>
__global__ void __launch_bounds__(256, 2)
mma_gemm(const __half* __restrict__ Ag, const __half* __restrict__ Bg,
         const float* __restrict__ biasg, CT* __restrict__ Cg,
         int M, int N, int K, int lda, int ldb, int ldc,
         const __half* Bg2, const float* bias2, CT* Cg2,
         const __half* Bg3, const float* bias3, CT* Cg3)
{
    constexpr int BM = 128, BK = 32, STAGES = 4;
    constexpr int STR = 20;
    constexpr int TSZ = BM * STR;

    extern __shared__ unsigned smem_u[];
    unsigned* AsB = smem_u;
    unsigned* BsB = smem_u + STAGES * TSZ;

    const int tid  = threadIdx.x;
    const int wid  = tid >> 5;
    const int lane = tid & 31;
    const int g    = lane >> 2;
    const int tq   = lane & 3;
    const int m0   = NGUARD ? blockIdx.x * BM : blockIdx.y * BM;
    const int n0   = NGUARD ? blockIdx.y * BM : blockIdx.x * BM;
    const int z    = blockIdx.z;

    const __half* A = Ag;
    const __half* B = Bg;
    const float* bias = biasg;
    CT* C = Cg;

    if (QKV) {
        if (z == 1) { B = Bg2; bias = bias2; C = Cg2; }
        else if (z == 2) { B = Bg3; bias = bias3; C = Cg3; }
    } else if (SPLITK > 1) {
        C = Cg + (long long)z * M * ldc;
    }

    const int rowbase = (wid & 3) * 32;
    const int colbase = (wid >> 2) * 64;

    float acc[2][8][4];
    #pragma unroll
    for (int i = 0; i < 2; i++)
        #pragma unroll
        for (int j = 0; j < 8; j++)
            #pragma unroll
            for (int qq = 0; qq < 4; qq++) acc[i][j][qq] = 0.0f;

    int kbeg = 0, kend = K;
    if (SPLITK > 1) { kbeg = z * (K / SPLITK); kend = kbeg + K / SPLITK; }
    const int ntiles = (kend - kbeg) / BK;

    auto issue_stage = [&](int stage, int k0) {
        unsigned* as = AsB + stage * TSZ;
        unsigned* bs = BsB + stage * TSZ;
        #pragma unroll
        for (int i = 0; i < 2; i++) {
            int c = tid + i * 256;
            int row = c >> 2, ch = c & 3;
            cp16(&as[row * STR + ch * 4],
                 A + (long long)(m0 + row) * lda + k0 + ch * 8, true);
        }
        #pragma unroll
        for (int i = 0; i < 2; i++) {
            int c = tid + i * 256;
            int row = c >> 2, ch = c & 3;
            bool ok = !NGUARD || (n0 + row) < N;
            cp16(&bs[row * STR + ch * 4],
                 B + (long long)(n0 + row) * ldb + k0 + ch * 8, ok);
        }
        cp_commit();
    };

    const int lrow  = (lane & 7) + ((lane >> 3) & 1) * 8;
    const int lkoff = ((lane >> 4) & 1) * 16;
    const uint32_t offA = (uint32_t)((rowbase + lrow) * 80 + lkoff);
    const uint32_t offB = (uint32_t)((colbase + lrow) * 80 + lkoff);
    const uint32_t smemA = (uint32_t)__cvta_generic_to_shared(AsB);
    const uint32_t smemB = (uint32_t)__cvta_generic_to_shared(BsB);

    issue_stage(0, kbeg);
    if (ntiles > 1) issue_stage(1, kbeg + BK);
    if (ntiles > 2) issue_stage(2, kbeg + 2 * BK);

    for (int t = 0; t < ntiles; t++) {
        int rem = ntiles - 1 - t;
        if (rem >= 2)
            asm volatile("cp.async.wait_group 2;\n" ::: "memory");
        else if (rem == 1)
            asm volatile("cp.async.wait_group 1;\n" ::: "memory");
        else
            asm volatile("cp.async.wait_group 0;\n" ::: "memory");
        __syncthreads();

        if (t + 3 < ntiles) issue_stage((t + 3) % STAGES, kbeg + (t + 3) * BK);

        const uint32_t aBase = smemA + (uint32_t)((t % STAGES) * TSZ * 4) + offA;
        const uint32_t bBase = smemB + (uint32_t)((t % STAGES) * TSZ * 4) + offB;

        #pragma unroll
        for (int ks2 = 0; ks2 < 2; ks2++) {
            const uint32_t ko = ks2 * 32;
            unsigned af[2][4];
            ldsm4(af[0], aBase + ko);
            ldsm4(af[1], aBase + ko + 1280);
            unsigned bf[8][2];
            #pragma unroll
            for (int p = 0; p < 4; p++) {
                unsigned tmp[4];
                ldsm4(tmp, bBase + ko + p * 1280);
                bf[2 * p][0]     = tmp[0];
                bf[2 * p + 1][0] = tmp[1];
                bf[2 * p][1]     = tmp[2];
                bf[2 * p + 1][1] = tmp[3];
            }
            #pragma unroll
            for (int i = 0; i < 2; i++)
                #pragma unroll
                for (int j = 0; j < 8; j++)
                    mma_f16(acc[i][j], af[i], bf[j]);
        }
    }

    #pragma unroll
    for (int i = 0; i < 2; i++) {
        #pragma unroll
        for (int j = 0; j < 8; j++) {
            int r = m0 + rowbase + i * 16 + g;
            int c = n0 + colbase + j * 8 + tq * 2;
            #pragma unroll
            for (int hh = 0; hh < 2; hh++) {
                int rr = r + hh * 8;
                float v0 = acc[i][j][hh * 2 + 0];
                float v1 = acc[i][j][hh * 2 + 1];
                if constexpr (SPLITK > 1) {
                    *(float2*)((float*)C + (long long)rr * ldc + c) = make_float2(v0, v1);
                } else {
                    if (bias) { v0 += bias[c]; v1 += bias[c + 1]; }
                    if (GELU_ACT) { v0 = gelu_exact(v0); v1 = gelu_exact(v1); }
                    if constexpr (NGUARD) {
                        float* Cf = (float*)C;
                        if (c < N)     Cf[(long long)rr * ldc + c]     = v0;
                        if (c + 1 < N) Cf[(long long)rr * ldc + c + 1] = v1;
                    } else if constexpr (sizeof(CT) == 2) {
                        *(__half2*)((__half*)C + (long long)rr * ldc + c) =
                            __floats2half2_rn(v0, v1);
                    } else {
                        *(float2*)((float*)C + (long long)rr * ldc + c) =
                            make_float2(v0, v1);
                    }
                }
            }
        }
    }
}

// ---------------------------------------------------------------------------
// Split-K reduce (plain) and fused reduce+LayerNorm
// ---------------------------------------------------------------------------
__global__ void reduce_splitk(const float* __restrict__ part,
                              const float* __restrict__ bias,
                              float* __restrict__ x, __half* __restrict__ xr,
                              int NN, int ldc) {
    int idx = (blockIdx.x * 256 + threadIdx.x) * 4;
    float4 p0 = *(const float4*)(part + idx);
    float4 p1 = *(const float4*)(part + idx + NN);
    float4 xv = *(const float4*)(x + idx);
    float4 bv = *(const float4*)(bias + (idx % ldc));
    float4 o;
    o.x = xv.x + p0.x + p1.x + bv.x;
    o.y = xv.y + p0.y + p1.y + bv.y;
    o.z = xv.z + p0.z + p1.z + bv.z;
    o.w = xv.w + p0.w + p1.w + bv.w;
    *(float4*)(x + idx) = o;
    *(__half2*)(xr + idx)     = __floats2half2_rn(o.x, o.y);
    *(__half2*)(xr + idx + 2) = __floats2half2_rn(o.z, o.w);
}

__global__ void reduce_ln_kernel(const float* __restrict__ part,
                                 const float* __restrict__ bias,
                                 float* __restrict__ x, __half* __restrict__ xr,
                                 const float* __restrict__ g,
                                 const float* __restrict__ bb,
                                 __half* __restrict__ lnout, int NN) {
    const int row = blockIdx.x;
    const int tid = threadIdx.x;
    const int idx = row * D_ + tid * 4;
    __shared__ float rs[256];
    __shared__ float rq[256];

    float4 p0 = *(const float4*)(part + idx);
    float4 p1 = *(const float4*)(part + idx + NN);
    float4 xv = *(const float4*)(x + idx);
    float4 bv = *(const float4*)(bias + tid * 4);
    float4 o;
    o.x = xv.x + p0.x + p1.x + bv.x;
    o.y = xv.y + p0.y + p1.y + bv.y;
    o.z = xv.z + p0.z + p1.z + bv.z;
    o.w = xv.w + p0.w + p1.w + bv.w;
    *(float4*)(x + idx) = o;
    *(__half2*)(xr + idx)     = __floats2half2_rn(o.x, o.y);
    *(__half2*)(xr + idx + 2) = __floats2half2_rn(o.z, o.w);

    float s  = o.x + o.y + o.z + o.w;
    float sq = o.x * o.x + o.y * o.y + o.z * o.z + o.w * o.w;
    rs[tid] = s; rq[tid] = sq;
    __syncthreads();
    for (int off = 128; off > 0; off >>= 1) {
        if (tid < off) { rs[tid] += rs[tid + off]; rq[tid] += rq[tid + off]; }
        __syncthreads();
    }
    float mu  = rs[0] * (1.0f / D_);
    float var = rq[0] * (1.0f / D_) - mu * mu;
    float rstd = rsqrtf(var + 1e-5f);

    int c = tid * 4;
    float4 gv = *(const float4*)(g + c);
    float4 bv2 = *(const float4*)(bb + c);
    float o0 = (o.x - mu) * rstd * gv.x + bv2.x;
    float o1 = (o.y - mu) * rstd * gv.y + bv2.y;
    float o2 = (o.z - mu) * rstd * gv.z + bv2.z;
    float o3 = (o.w - mu) * rstd * gv.w + bv2.w;
    __half* op = lnout + (size_t)row * D_ + c;
    *(__half2*)(op)     = __floats2half2_rn(o0, o1);
    *(__half2*)(op + 2) = __floats2half2_rn(o2, o3);
}

// ---------------------------------------------------------------------------
// Host launcher — R9 config + dual-stream prepass overlap
// ---------------------------------------------------------------------------
extern "C" void kernel_launch(void* const* d_in, const int* in_sizes, int n_in,
                              void* d_out, int out_size) {
    const int*   idx   = (const int*)  d_in[0];
    const float* te    = (const float*)d_in[1];
    const float* pe    = (const float*)d_in[2];
    const float* wq    = (const float*)d_in[3];
    const float* bq    = (const float*)d_in[4];
    const float* wk    = (const float*)d_in[5];
    const float* bk    = (const float*)d_in[6];
    const float* wv    = (const float*)d_in[7];
    const float* bv    = (const float*)d_in[8];
    const float* wo    = (const float*)d_in[9];
    const float* bo    = (const float*)d_in[10];
    const float* ln2g  = (const float*)d_in[11];
    const float* ln2b  = (const float*)d_in[12];
    const float* w1    = (const float*)d_in[13];
    const float* b1    = (const float*)d_in[14];
    const float* w2    = (const float*)d_in[15];
    const float* b2    = (const float*)d_in[16];
    const float* lnfg  = (const float*)d_in[17];
    const float* lnfb  = (const float*)d_in[18];
    float* out = (float*)d_out;

    float *x, *p;
    __half *xr, *q, *k, *v, *y, *ln, *h1;
    __half *wqT, *wkT, *wvT, *woT, *w1T, *w2T, *teh;
    cudaGetSymbolAddress((void**)&x,  g_x);
    cudaGetSymbolAddress((void**)&xr, g_xr);
    cudaGetSymbolAddress((void**)&q,  g_q);
    cudaGetSymbolAddress((void**)&k,  g_k);
    cudaGetSymbolAddress((void**)&v,  g_v);
    cudaGetSymbolAddress((void**)&y,  g_y);
    cudaGetSymbolAddress((void**)&ln, g_ln);
    cudaGetSymbolAddress((void**)&h1, g_h1);
    cudaGetSymbolAddress((void**)&p,  g_p);
    cudaGetSymbolAddress((void**)&wqT, g_wqT);
    cudaGetSymbolAddress((void**)&wkT, g_wkT);
    cudaGetSymbolAddress((void**)&wvT, g_wvT);
    cudaGetSymbolAddress((void**)&woT, g_woT);
    cudaGetSymbolAddress((void**)&w1T, g_w1T);
    cudaGetSymbolAddress((void**)&w2T, g_w2T);
    cudaGetSymbolAddress((void**)&teh, g_teh);

    const size_t smem_sz = 4 * 2 * 128 * 20 * 4;   // 81920

    auto kq  = mma_gemm<__half, false, true,  1, false>;
    auto ksk = mma_gemm<float,  false, false, 2, false>;
    auto kw1 = mma_gemm<__half, true,  false, 1, false>;
    auto klg = mma_gemm<float,  false, false, 1, true>;
    cudaFuncSetAttribute(kq,  cudaFuncAttributeMaxDynamicSharedMemorySize, (int)smem_sz);
    cudaFuncSetAttribute(ksk, cudaFuncAttributeMaxDynamicSharedMemorySize, (int)smem_sz);
    cudaFuncSetAttribute(kw1, cudaFuncAttributeMaxDynamicSharedMemorySize, (int)smem_sz);
    cudaFuncSetAttribute(klg, cudaFuncAttributeMaxDynamicSharedMemorySize, (int)smem_sz);

    static cudaStream_t s2 = nullptr;
    static cudaEvent_t evF = nullptr, evA = nullptr, evB = nullptr;
    if (!s2) {
        cudaStreamCreateWithFlags(&s2, cudaStreamNonBlocking);
        cudaEventCreateWithFlags(&evF, cudaEventDisableTiming);
        cudaEventCreateWithFlags(&evA, cudaEventDisableTiming);
        cudaEventCreateWithFlags(&evB, cudaEventDisableTiming);
    }

    dim3 tb(32, 8);
    cudaEventRecord(evF, 0);
    cudaStreamWaitEvent(s2, evF, 0);

    // side stream: layer-0 weights first
    transpose_cvt<<<dim3(32, 32, 1), tb, 0, s2>>>(wq, wqT, D_, D_);
    transpose_cvt<<<dim3(32, 32, 1), tb, 0, s2>>>(wk, wkT, D_, D_);
    transpose_cvt<<<dim3(32, 32, 1), tb, 0, s2>>>(wv, wvT, D_, D_);
    transpose_cvt<<<dim3(32, 32, 1), tb, 0, s2>>>(wo, woT, D_, D_);
    transpose_cvt<<<dim3(DFF_ / 32, D_ / 32, 1), tb, 0, s2>>>(w1, w1T, D_, DFF_);
    transpose_cvt<<<dim3(D_ / 32, DFF_ / 32, 1), tb, 0, s2>>>(w2, w2T, DFF_, D_);
    cudaEventRecord(evA, s2);

    // side stream: layers 1..3 + te cast (overlaps layer-0 compute)
    transpose_cvt<<<dim3(32, 32, L_ - 1), tb, 0, s2>>>(wq + (size_t)D_ * D_, wqT + (size_t)D_ * D_, D_, D_);
    transpose_cvt<<<dim3(32, 32, L_ - 1), tb, 0, s2>>>(wk + (size_t)D_ * D_, wkT + (size_t)D_ * D_, D_, D_);
    transpose_cvt<<<dim3(32, 32, L_ - 1), tb, 0, s2>>>(wv + (size_t)D_ * D_, wvT + (size_t)D_ * D_, D_, D_);
    transpose_cvt<<<dim3(32, 32, L_ - 1), tb, 0, s2>>>(wo + (size_t)D_ * D_, woT + (size_t)D_ * D_, D_, D_);
    transpose_cvt<<<dim3(DFF_ / 32, D_ / 32, L_ - 1), tb, 0, s2>>>(w1 + (size_t)D_ * DFF_, w1T + (size_t)D_ * DFF_, D_, DFF_);
    transpose_cvt<<<dim3(D_ / 32, DFF_ / 32, L_ - 1), tb, 0, s2>>>(w2 + (size_t)DFF_ * D_, w2T + (size_t)DFF_ * D_, DFF_, D_);
    {
        long long nte = (long long)V_ * D_;
        int gte = (int)((nte + 2047) / 2048);
        cvt_f16_kernel<<<gte, 256, 0, s2>>>(te, teh, nte);
    }
    cudaEventRecord(evB, s2);

    embed_kernel<<<NTOK, 256>>>(idx, te, pe, x, xr);

    const dim3 gQKV(D_ / 128, NTOK / 128, 3);
    const dim3 gSK (D_ / 128, NTOK / 128, 2);
    const dim3 gF  (DFF_ / 128, NTOK / 128);
    const dim3 gFA (S_ / 128, B_ * H_);
    const dim3 gLg (NTOK / 128, (V_ + 127) / 128);
    const int NN = NTOK * D_;

    for (int l = 0; l < L_; l++) {
        if (l == 0) cudaStreamWaitEvent(0, evA, 0);
        if (l == 1) cudaStreamWaitEvent(0, evB, 0);

        const __half* wq_l = wqT + (size_t)l * D_ * D_;
        const __half* wk_l = wkT + (size_t)l * D_ * D_;
        const __half* wv_l = wvT + (size_t)l * D_ * D_;
        const __half* wo_l = woT + (size_t)l * D_ * D_;
        const __half* w1_l = w1T + (size_t)l * D_ * DFF_;
        const __half* w2_l = w2T + (size_t)l * DFF_ * D_;

        kq<<<gQKV, 256, smem_sz>>>(
            xr, wq_l, bq + l * D_, q, NTOK, D_, D_, D_, D_, D_,
            wk_l, bk + l * D_, k, wv_l, bv + l * D_, v);

        flash_attn<<<gFA, 256>>>(q, k, v, y);

        ksk<<<gSK, 256, smem_sz>>>(
            y, wo_l, nullptr, p, NTOK, D_, D_, D_, D_, D_,
            nullptr, nullptr, nullptr, nullptr, nullptr, nullptr);
        reduce_ln_kernel<<<NTOK, 256>>>(p, bo + l * D_, x, xr,
                                        ln2g + l * D_, ln2b + l * D_, ln, NN);

        kw1<<<gF, 256, smem_sz>>>(
            ln, w1_l, b1 + l * DFF_, h1, NTOK, DFF_, D_, D_, D_, DFF_,
            nullptr, nullptr, nullptr, nullptr, nullptr, nullptr);

        ksk<<<gSK, 256, smem_sz>>>(
            h1, w2_l, nullptr, p, NTOK, D_, DFF_, DFF_, DFF_, D_,
            nullptr, nullptr, nullptr, nullptr, nullptr, nullptr);
        if (l < L_ - 1) {
            reduce_splitk<<<NN / 1024, 256>>>(p, b2 + l * D_, x, xr, NN, D_);
        } else {
            reduce_ln_kernel<<<NTOK, 256>>>(p, b2 + l * D_, x, xr,
                                            lnfg, lnfb, ln, NN);
        }
    }

    // logits = lnf(x) @ te^T  (m fastest: te L2 reuse)
    klg<<<gLg, 256, smem_sz>>>(
        ln, teh, nullptr, out, NTOK, V_, D_, D_, D_, V_,
        nullptr, nullptr, nullptr, nullptr, nullptr, nullptr);
}

// round 13
// speedup vs baseline: 1.1404x; 1.0859x over previous
#include <cuda_runtime.h>
#include <cuda_fp16.h>
#include <cuda_bf16.h>
#include <math.h>
#include <stdint.h>

#define D_   1024
#define H_   16
#define V_   50257
#define L_   4
#define B_   2
#define S_   1024
#define DK_  64
#define DFF_ 4096
#define NTOK (B_ * S_)
#define NEGF (-3.402823466e38f)

// ---------------------------------------------------------------------------
// Device scratch
// ---------------------------------------------------------------------------
__device__ float  g_x [NTOK * D_];
__device__ __half g_xr[NTOK * D_];
__device__ __half g_q [NTOK * D_];
__device__ __half g_k [NTOK * D_];
__device__ __half g_v [NTOK * D_];
__device__ __half g_y [NTOK * D_];
__device__ __half g_ln[NTOK * D_];
__device__ __half g_h1[NTOK * DFF_];
__device__ float  g_p [2 * NTOK * D_];
__device__ __half g_wqT[L_ * D_ * D_];
__device__ __half g_wkT[L_ * D_ * D_];
__device__ __half g_wvT[L_ * D_ * D_];
__device__ __half g_woT[L_ * D_ * D_];
__device__ __half g_w1T[L_ * D_ * DFF_];
__device__ __half g_w2T[L_ * DFF_ * D_];
__device__ __half g_teh[(size_t)V_ * D_];

__device__ __forceinline__ float gelu_exact(float v) {
    return 0.5f * v * (1.0f + erff(v * 0.70710678118654752440f));
}

__device__ __forceinline__ void mma_f16(float* c, const unsigned* a, const unsigned* b) {
    asm volatile(
        "mma.sync.aligned.m16n8k16.row.col.f32.f16.f16.f32 "
        "{%0,%1,%2,%3},{%4,%5,%6,%7},{%8,%9},{%0,%1,%2,%3};"
        : "+f"(c[0]), "+f"(c[1]), "+f"(c[2]), "+f"(c[3])
        : "r"(a[0]), "r"(a[1]), "r"(a[2]), "r"(a[3]), "r"(b[0]), "r"(b[1]));
}
__device__ __forceinline__ void ldsm4(unsigned* r, uint32_t addr) {
    asm volatile("ldmatrix.sync.aligned.m8n8.x4.shared.b16 {%0,%1,%2,%3}, [%4];"
        : "=r"(r[0]), "=r"(r[1]), "=r"(r[2]), "=r"(r[3]) : "r"(addr));
}
__device__ __forceinline__ void cp16(void* s, const void* g, bool pred) {
    unsigned sa = (unsigned)__cvta_generic_to_shared(s);
    int sz = pred ? 16 : 0;
    asm volatile("cp.async.cg.shared.global [%0], [%1], 16, %2;\n"
                 :: "r"(sa), "l"(g), "r"(sz));
}
__device__ __forceinline__ void cp_commit() {
    asm volatile("cp.async.commit_group;\n" ::: "memory");
}

// ---------------------------------------------------------------------------
// Prepass: transpose [K,N] fp32 -> [N,K] fp16 ; wide cast for te
// ---------------------------------------------------------------------------
__global__ void transpose_cvt(const float* __restrict__ in, __half* __restrict__ outp,
                              int K, int N) {
    __shared__ float t[32][33];
    long long zoff = (long long)blockIdx.z * K * N;
    in += zoff; outp += zoff;
    int k0 = blockIdx.y * 32, n0 = blockIdx.x * 32;
    int tx = threadIdx.x, ty = threadIdx.y;
    #pragma unroll
    for (int i = 0; i < 4; i++)
        t[ty + i * 8][tx] = in[(long long)(k0 + ty + i * 8) * N + n0 + tx];
    __syncthreads();
    #pragma unroll
    for (int i = 0; i < 4; i++)
        outp[(long long)(n0 + ty + i * 8) * K + k0 + tx] = __float2half(t[tx][ty + i * 8]);
}

__global__ void cvt_f16_kernel(const float* __restrict__ in, __half* __restrict__ outp,
                               long long NTOTAL) {
    long long i = ((long long)blockIdx.x * 256 + threadIdx.x) * 8;
    if (i + 8 <= NTOTAL) {
        float4 v0 = *(const float4*)(in + i);
        float4 v1 = *(const float4*)(in + i + 4);
        __half2 h0 = __floats2half2_rn(v0.x, v0.y);
        __half2 h1 = __floats2half2_rn(v0.z, v0.w);
        __half2 h2 = __floats2half2_rn(v1.x, v1.y);
        __half2 h3 = __floats2half2_rn(v1.z, v1.w);
        uint4 pk;
        pk.x = *(unsigned*)&h0; pk.y = *(unsigned*)&h1;
        pk.z = *(unsigned*)&h2; pk.w = *(unsigned*)&h3;
        *(uint4*)(outp + i) = pk;
    } else {
        for (long long e = i; e < NTOTAL; e++) outp[e] = __float2half(in[e]);
    }
}

// ---------------------------------------------------------------------------
// Embedding
// ---------------------------------------------------------------------------
__global__ void embed_kernel(const int* __restrict__ idx,
                             const float* __restrict__ te,
                             const float* __restrict__ pe,
                             float* __restrict__ x, __half* __restrict__ xr) {
    int row = blockIdx.x;
    int s   = row % S_;
    int tok = idx[row];
    int c   = threadIdx.x * 4;
    float4 t = *(const float4*)(te + (size_t)tok * D_ + c);
    float4 p = *(const float4*)(pe + (size_t)s   * D_ + c);
    float4 o = make_float4(t.x + p.x, t.y + p.y, t.z + p.z, t.w + p.w);
    *(float4*)(x + (size_t)row * D_ + c) = o;
    __half* xp = xr + (size_t)row * D_ + c;
    *(__half2*)(xp)     = __floats2half2_rn(o.x, o.y);
    *(__half2*)(xp + 2) = __floats2half2_rn(o.z, o.w);
}

// ---------------------------------------------------------------------------
// Fused flash attention (unchanged)
// ---------------------------------------------------------------------------
__global__ void __launch_bounds__(256, 2)
flash_attn(const __half* __restrict__ q, const __half* __restrict__ k,
           const __half* __restrict__ v, __half* __restrict__ y)
{
    __shared__ unsigned Ksu[64 * 36];
    __shared__ __half   Vsh[64 * 72];
    unsigned* Vsu = (unsigned*)Vsh;

    const int xmap[8] = {0, 7, 1, 6, 2, 5, 3, 4};
    const int m0  = xmap[blockIdx.x] * 128;
    const int bh  = blockIdx.y;
    const int b   = bh >> 4, h = bh & 15;
    const int tid = threadIdx.x;
    const int wid = tid >> 5, lane = tid & 31;
    const int g   = lane >> 2, tq = lane & 3;
    const int r0 = m0 + wid * 16 + g;
    const int r8 = r0 + 8;
    const int RS = H_ * DK_;

    unsigned qf[4][4];
    {
        const unsigned* q0u = (const unsigned*)(q + (size_t)(b * S_ + r0) * RS + h * DK_);
        const unsigned* q8u = q0u + 8 * (RS / 2);
        const __half2 sc = __float2half2_rn(0.125f);
        #pragma unroll
        for (int s = 0; s < 4; s++) {
            __half2 a0 = __hmul2(*(const __half2*)&q0u[s * 8 + tq], sc);
            __half2 a1 = __hmul2(*(const __half2*)&q8u[s * 8 + tq], sc);
            __half2 a2 = __hmul2(*(const __half2*)&q0u[s * 8 + tq + 4], sc);
            __half2 a3 = __hmul2(*(const __half2*)&q8u[s * 8 + tq + 4], sc);
            qf[s][0] = *(unsigned*)&a0; qf[s][1] = *(unsigned*)&a1;
            qf[s][2] = *(unsigned*)&a2; qf[s][3] = *(unsigned*)&a3;
        }
    }

    float o[8][4];
    #pragma unroll
    for (int j = 0; j < 8; j++)
        #pragma unroll
        for (int c = 0; c < 4; c++) o[j][c] = 0.0f;
    float mg = NEGF, m8 = NEGF, lg = 0.0f, l8 = 0.0f;

    const int ntiles = m0 / 64 + 2;

    for (int jt = 0; jt < ntiles; jt++) {
        const int t0 = jt * 64;
        {
            #pragma unroll
            for (int i = 0; i < 2; i++) {
                int c = tid + i * 256;
                int row = c >> 3, ch = c & 7;
                uint4 kv = *(const uint4*)(k + (size_t)(b * S_ + t0 + row) * RS
                                           + h * DK_ + ch * 8);
                *(uint4*)&Ksu[row * 36 + ch * 4] = kv;
            }
            int t = tid >> 2;
            int dc = (tid & 3) * 16;
            const __half* vsrc = v + (size_t)(b * S_ + t0 + t) * RS + h * DK_ + dc;
            uint4 v0 = *(const uint4*)(vsrc);
            uint4 v1 = *(const uint4*)(vsrc + 8);
            const __half* vh0 = (const __half*)&v0;
            const __half* vh1 = (const __half*)&v1;
            #pragma unroll
            for (int i = 0; i < 8; i++) {
                Vsh[(dc + i) * 72 + t]     = vh0[i];
                Vsh[(dc + 8 + i) * 72 + t] = vh1[i];
            }
        }
        __syncthreads();

        float s[8][4];
        #pragma unroll
        for (int j = 0; j < 8; j++)
            #pragma unroll
            for (int c = 0; c < 4; c++) s[j][c] = 0.0f;

        #pragma unroll
        for (int ks = 0; ks < 4; ks++) {
            #pragma unroll
            for (int jn = 0; jn < 8; jn++) {
                unsigned bf[2];
                bf[0] = Ksu[(8 * jn + g) * 36 + 8 * ks + tq];
                bf[1] = Ksu[(8 * jn + g) * 36 + 8 * ks + tq + 4];
                mma_f16(s[jn], qf[ks], bf);
            }
        }

        if (t0 + 63 > m0) {
            #pragma unroll
            for (int jn = 0; jn < 8; jn++) {
                int c0 = t0 + 8 * jn + 2 * tq;
                if (c0     > r0) s[jn][0] = NEGF;
                if (c0 + 1 > r0) s[jn][1] = NEGF;
                if (c0     > r8) s[jn][2] = NEGF;
                if (c0 + 1 > r8) s[jn][3] = NEGF;
            }
        }

        float tmg = NEGF, tm8 = NEGF;
        #pragma unroll
        for (int jn = 0; jn < 8; jn++) {
            tmg = fmaxf(tmg, fmaxf(s[jn][0], s[jn][1]));
            tm8 = fmaxf(tm8, fmaxf(s[jn][2], s[jn][3]));
        }
        tmg = fmaxf(tmg, __shfl_xor_sync(0xffffffffu, tmg, 1));
        tmg = fmaxf(tmg, __shfl_xor_sync(0xffffffffu, tmg, 2));
        tm8 = fmaxf(tm8, __shfl_xor_sync(0xffffffffu, tm8, 1));
        tm8 = fmaxf(tm8, __shfl_xor_sync(0xffffffffu, tm8, 2));

        float mgn = fmaxf(mg, tmg), m8n = fmaxf(m8, tm8);
        float ag = expf(mg - mgn), a8 = expf(m8 - m8n);

        float rsg = 0.0f, rs8 = 0.0f;
        #pragma unroll
        for (int jn = 0; jn < 8; jn++) {
            s[jn][0] = expf(s[jn][0] - mgn);
            s[jn][1] = expf(s[jn][1] - mgn);
            s[jn][2] = expf(s[jn][2] - m8n);
            s[jn][3] = expf(s[jn][3] - m8n);
            rsg += s[jn][0] + s[jn][1];
            rs8 += s[jn][2] + s[jn][3];
        }
        rsg += __shfl_xor_sync(0xffffffffu, rsg, 1);
        rsg += __shfl_xor_sync(0xffffffffu, rsg, 2);
        rs8 += __shfl_xor_sync(0xffffffffu, rs8, 1);
        rs8 += __shfl_xor_sync(0xffffffffu, rs8, 2);

        lg = lg * ag + rsg;
        l8 = l8 * a8 + rs8;
        mg = mgn; m8 = m8n;

        #pragma unroll
        for (int jd = 0; jd < 8; jd++) {
            o[jd][0] *= ag; o[jd][1] *= ag;
            o[jd][2] *= a8; o[jd][3] *= a8;
        }

        #pragma unroll
        for (int u = 0; u < 4; u++) {
            unsigned af[4];
            __half2 p0 = __floats2half2_rn(s[2 * u][0], s[2 * u][1]);
            __half2 p1 = __floats2half2_rn(s[2 * u][2], s[2 * u][3]);
            __half2 p2 = __floats2half2_rn(s[2 * u + 1][0], s[2 * u + 1][1]);
            __half2 p3 = __floats2half2_rn(s[2 * u + 1][2], s[2 * u + 1][3]);
            af[0] = *(unsigned*)&p0; af[1] = *(unsigned*)&p1;
            af[2] = *(unsigned*)&p2; af[3] = *(unsigned*)&p3;
            #pragma unroll
            for (int jd = 0; jd < 8; jd++) {
                unsigned bf[2];
                bf[0] = Vsu[(8 * jd + g) * 36 + 8 * u + tq];
                bf[1] = Vsu[(8 * jd + g) * 36 + 8 * u + tq + 4];
                mma_f16(o[jd], af, bf);
            }
        }
        __syncthreads();
    }

    float ig = 1.0f / lg, i8 = 1.0f / l8;
    __half* y0 = y + (size_t)(b * S_ + r0) * RS + h * DK_;
    __half* y8 = y0 + 8 * RS;
    #pragma unroll
    for (int jd = 0; jd < 8; jd++) {
        *(__half2*)(y0 + 8 * jd + 2 * tq) =
            __floats2half2_rn(o[jd][0] * ig, o[jd][1] * ig);
        *(__half2*)(y8 + 8 * jd + 2 * tq) =
            __floats2half2_rn(o[jd][2] * i8, o[jd][3] * i8);
    }
}

// ---------------------------------------------------------------------------
// FP16 MMA GEMM: 128x128 tile, BK=64, 3-stage cp.async, ldmatrix.
// Smem row = 144 B (64 halves + 8 pad): conflict-free LDSM (rows mod 128B
// hit banks 0,16,..,112). Halves the sync count vs BK=32.
// ---------------------------------------------------------------------------
template <typename CT, bool GELU_ACT, bool QKV, int SPLITK, bool NGUARD>
__global__ void __launch_bounds__(256, 2)
mma_gemm(const __half* __restrict__ Ag, const __half* __restrict__ Bg,
         const float* __restrict__ biasg, CT* __restrict__ Cg,
         int M, int N, int K, int lda, int ldb, int ldc,
         const __half* Bg2, const float* bias2, CT* Cg2,
         const __half* Bg3, const float* bias3, CT* Cg3)
{
    constexpr int BM = 128, BK = 64, STAGES = 3;
    constexpr int STR = 36;                  // half2 units per row (144 B)
    constexpr int TSZ = BM * STR;            // per-stage units (A or B)
    constexpr int ROWB = 144;                // row bytes

    extern __shared__ unsigned smem_u[];
    unsigned* AsB = smem_u;
    unsigned* BsB = smem_u + STAGES * TSZ;

    const int tid  = threadIdx.x;
    const int wid  = tid >> 5;
    const int lane = tid & 31;
    const int g    = lane >> 2;
    const int tq   = lane & 3;
    const int m0   = NGUARD ? blockIdx.x * BM : blockIdx.y * BM;
    const int n0   = NGUARD ? blockIdx.y * BM : blockIdx.x * BM;
    const int z    = blockIdx.z;

    const __half* A = Ag;
    const __half* B = Bg;
    const float* bias = biasg;
    CT* C = Cg;

    if (QKV) {
        if (z == 1) { B = Bg2; bias = bias2; C = Cg2; }
        else if (z == 2) { B = Bg3; bias = bias3; C = Cg3; }
    } else if (SPLITK > 1) {
        C = Cg + (long long)z * M * ldc;
    }

    const int rowbase = (wid & 3) * 32;
    const int colbase = (wid >> 2) * 64;

    float acc[2][8][4];
    #pragma unroll
    for (int i = 0; i < 2; i++)
        #pragma unroll
        for (int j = 0; j < 8; j++)
            #pragma unroll
            for (int qq = 0; qq < 4; qq++) acc[i][j][qq] = 0.0f;

    int kbeg = 0, kend = K;
    if (SPLITK > 1) { kbeg = z * (K / SPLITK); kend = kbeg + K / SPLITK; }
    const int ntiles = (kend - kbeg) / BK;

    auto issue_stage = [&](int stage, int k0) {
        unsigned* as = AsB + stage * TSZ;
        unsigned* bs = BsB + stage * TSZ;
        #pragma unroll
        for (int i = 0; i < 4; i++) {        // A: 1024 chunks = 128 rows x 8
            int c = tid + i * 256;
            int row = c >> 3, ch = c & 7;
            cp16(&as[row * STR + ch * 4],
                 A + (long long)(m0 + row) * lda + k0 + ch * 8, true);
        }
        #pragma unroll
        for (int i = 0; i < 4; i++) {
            int c = tid + i * 256;
            int row = c >> 3, ch = c & 7;
            bool ok = !NGUARD || (n0 + row) < N;
            cp16(&bs[row * STR + ch * 4],
                 B + (long long)(n0 + row) * ldb + k0 + ch * 8, ok);
        }
        cp_commit();
    };

    const int lrow  = (lane & 7) + ((lane >> 3) & 1) * 8;
    const int lkoff = ((lane >> 4) & 1) * 16;
    const uint32_t offA = (uint32_t)((rowbase + lrow) * ROWB + lkoff);
    const uint32_t offB = (uint32_t)((colbase + lrow) * ROWB + lkoff);
    const uint32_t smemA = (uint32_t)__cvta_generic_to_shared(AsB);
    const uint32_t smemB = (uint32_t)__cvta_generic_to_shared(BsB);

    issue_stage(0, kbeg);
    if (ntiles > 1) issue_stage(1, kbeg + BK);

    for (int t = 0; t < ntiles; t++) {
        if (t == ntiles - 1)
            asm volatile("cp.async.wait_group 0;\n" ::: "memory");
        else
            asm volatile("cp.async.wait_group 1;\n" ::: "memory");
        __syncthreads();

        if (t + 2 < ntiles) issue_stage((t + 2) % STAGES, kbeg + (t + 2) * BK);

        const uint32_t aBase = smemA + (uint32_t)((t % STAGES) * TSZ * 4) + offA;
        const uint32_t bBase = smemB + (uint32_t)((t % STAGES) * TSZ * 4) + offB;

        #pragma unroll
        for (int ks2 = 0; ks2 < 4; ks2++) {   // four k16 windows per BK=64
            const uint32_t ko = ks2 * 32;
            unsigned af[2][4];
            ldsm4(af[0], aBase + ko);
            ldsm4(af[1], aBase + ko + 16 * ROWB);
            unsigned bf[8][2];
            #pragma unroll
            for (int p = 0; p < 4; p++) {
                unsigned tmp[4];
                ldsm4(tmp, bBase + ko + p * 16 * ROWB);
                bf[2 * p][0]     = tmp[0];
                bf[2 * p + 1][0] = tmp[1];
                bf[2 * p][1]     = tmp[2];
                bf[2 * p + 1][1] = tmp[3];
            }
            #pragma unroll
            for (int i = 0; i < 2; i++)
                #pragma unroll
                for (int j = 0; j < 8; j++)
                    mma_f16(acc[i][j], af[i], bf[j]);
        }
    }

    #pragma unroll
    for (int i = 0; i < 2; i++) {
        #pragma unroll
        for (int j = 0; j < 8; j++) {
            int r = m0 + rowbase + i * 16 + g;
            int c = n0 + colbase + j * 8 + tq * 2;
            #pragma unroll
            for (int hh = 0; hh < 2; hh++) {
                int rr = r + hh * 8;
                float v0 = acc[i][j][hh * 2 + 0];
                float v1 = acc[i][j][hh * 2 + 1];
                if constexpr (SPLITK > 1) {
                    *(float2*)((float*)C + (long long)rr * ldc + c) = make_float2(v0, v1);
                } else {
                    if (bias) { v0 += bias[c]; v1 += bias[c + 1]; }
                    if (GELU_ACT) { v0 = gelu_exact(v0); v1 = gelu_exact(v1); }
                    if constexpr (NGUARD) {
                        float* Cf = (float*)C;
                        if (c < N)     Cf[(long long)rr * ldc + c]     = v0;
                        if (c + 1 < N) Cf[(long long)rr * ldc + c + 1] = v1;
                    } else if constexpr (sizeof(CT) == 2) {
                        *(__half2*)((__half*)C + (long long)rr * ldc + c) =
                            __floats2half2_rn(v0, v1);
                    } else {
                        *(float2*)((float*)C + (long long)rr * ldc + c) =
                            make_float2(v0, v1);
                    }
                }
            }
        }
    }
}

// ---------------------------------------------------------------------------
// Split-K reduce (plain) and fused reduce+LayerNorm
// ---------------------------------------------------------------------------
__global__ void reduce_splitk(const float* __restrict__ part,
                              const float* __restrict__ bias,
                              float* __restrict__ x, __half* __restrict__ xr,
                              int NN, int ldc) {
    int idx = (blockIdx.x * 256 + threadIdx.x) * 4;
    float4 p0 = *(const float4*)(part + idx);
    float4 p1 = *(const float4*)(part + idx + NN);
    float4 xv = *(const float4*)(x + idx);
    float4 bv = *(const float4*)(bias + (idx % ldc));
    float4 o;
    o.x = xv.x + p0.x + p1.x + bv.x;
    o.y = xv.y + p0.y + p1.y + bv.y;
    o.z = xv.z + p0.z + p1.z + bv.z;
    o.w = xv.w + p0.w + p1.w + bv.w;
    *(float4*)(x + idx) = o;
    *(__half2*)(xr + idx)     = __floats2half2_rn(o.x, o.y);
    *(__half2*)(xr + idx + 2) = __floats2half2_rn(o.z, o.w);
}

__global__ void reduce_ln_kernel(const float* __restrict__ part,
                                 const float* __restrict__ bias,
                                 float* __restrict__ x, __half* __restrict__ xr,
                                 const float* __restrict__ g,
                                 const float* __restrict__ bb,
                                 __half* __restrict__ lnout, int NN) {
    const int row = blockIdx.x;
    const int tid = threadIdx.x;
    const int idx = row * D_ + tid * 4;
    __shared__ float rs[256];
    __shared__ float rq[256];

    float4 p0 = *(const float4*)(part + idx);
    float4 p1 = *(const float4*)(part + idx + NN);
    float4 xv = *(const float4*)(x + idx);
    float4 bv = *(const float4*)(bias + tid * 4);
    float4 o;
    o.x = xv.x + p0.x + p1.x + bv.x;
    o.y = xv.y + p0.y + p1.y + bv.y;
    o.z = xv.z + p0.z + p1.z + bv.z;
    o.w = xv.w + p0.w + p1.w + bv.w;
    *(float4*)(x + idx) = o;
    *(__half2*)(xr + idx)     = __floats2half2_rn(o.x, o.y);
    *(__half2*)(xr + idx + 2) = __floats2half2_rn(o.z, o.w);

    float s  = o.x + o.y + o.z + o.w;
    float sq = o.x * o.x + o.y * o.y + o.z * o.z + o.w * o.w;
    rs[tid] = s; rq[tid] = sq;
    __syncthreads();
    for (int off = 128; off > 0; off >>= 1) {
        if (tid < off) { rs[tid] += rs[tid + off]; rq[tid] += rq[tid + off]; }
        __syncthreads();
    }
    float mu  = rs[0] * (1.0f / D_);
    float var = rq[0] * (1.0f / D_) - mu * mu;
    float rstd = rsqrtf(var + 1e-5f);

    int c = tid * 4;
    float4 gv = *(const float4*)(g + c);
    float4 bv2 = *(const float4*)(bb + c);
    float o0 = (o.x - mu) * rstd * gv.x + bv2.x;
    float o1 = (o.y - mu) * rstd * gv.y + bv2.y;
    float o2 = (o.z - mu) * rstd * gv.z + bv2.z;
    float o3 = (o.w - mu) * rstd * gv.w + bv2.w;
    __half* op = lnout + (size_t)row * D_ + c;
    *(__half2*)(op)     = __floats2half2_rn(o0, o1);
    *(__half2*)(op + 2) = __floats2half2_rn(o2, o3);
}

// ---------------------------------------------------------------------------
// Host launcher — BK=64 GEMMs + 3-level prepass gating
// ---------------------------------------------------------------------------
extern "C" void kernel_launch(void* const* d_in, const int* in_sizes, int n_in,
                              void* d_out, int out_size) {
    const int*   idx   = (const int*)  d_in[0];
    const float* te    = (const float*)d_in[1];
    const float* pe    = (const float*)d_in[2];
    const float* wq    = (const float*)d_in[3];
    const float* bq    = (const float*)d_in[4];
    const float* wk    = (const float*)d_in[5];
    const float* bk    = (const float*)d_in[6];
    const float* wv    = (const float*)d_in[7];
    const float* bv    = (const float*)d_in[8];
    const float* wo    = (const float*)d_in[9];
    const float* bo    = (const float*)d_in[10];
    const float* ln2g  = (const float*)d_in[11];
    const float* ln2b  = (const float*)d_in[12];
    const float* w1    = (const float*)d_in[13];
    const float* b1    = (const float*)d_in[14];
    const float* w2    = (const float*)d_in[15];
    const float* b2    = (const float*)d_in[16];
    const float* lnfg  = (const float*)d_in[17];
    const float* lnfb  = (const float*)d_in[18];
    float* out = (float*)d_out;

    float *x, *p;
    __half *xr, *q, *k, *v, *y, *ln, *h1;
    __half *wqT, *wkT, *wvT, *woT, *w1T, *w2T, *teh;
    cudaGetSymbolAddress((void**)&x,  g_x);
    cudaGetSymbolAddress((void**)&xr, g_xr);
    cudaGetSymbolAddress((void**)&q,  g_q);
    cudaGetSymbolAddress((void**)&k,  g_k);
    cudaGetSymbolAddress((void**)&v,  g_v);
    cudaGetSymbolAddress((void**)&y,  g_y);
    cudaGetSymbolAddress((void**)&ln, g_ln);
    cudaGetSymbolAddress((void**)&h1, g_h1);
    cudaGetSymbolAddress((void**)&p,  g_p);
    cudaGetSymbolAddress((void**)&wqT, g_wqT);
    cudaGetSymbolAddress((void**)&wkT, g_wkT);
    cudaGetSymbolAddress((void**)&wvT, g_wvT);
    cudaGetSymbolAddress((void**)&woT, g_woT);
    cudaGetSymbolAddress((void**)&w1T, g_w1T);
    cudaGetSymbolAddress((void**)&w2T, g_w2T);
    cudaGetSymbolAddress((void**)&teh, g_teh);

    const size_t smem_sz = 3 * 2 * 128 * 36 * 4;   // 110592 B

    auto kq  = mma_gemm<__half, false, true,  1, false>;
    auto ksk = mma_gemm<float,  false, false, 2, false>;
    auto kw1 = mma_gemm<__half, true,  false, 1, false>;
    auto klg = mma_gemm<float,  false, false, 1, true>;
    cudaFuncSetAttribute(kq,  cudaFuncAttributeMaxDynamicSharedMemorySize, (int)smem_sz);
    cudaFuncSetAttribute(ksk, cudaFuncAttributeMaxDynamicSharedMemorySize, (int)smem_sz);
    cudaFuncSetAttribute(kw1, cudaFuncAttributeMaxDynamicSharedMemorySize, (int)smem_sz);
    cudaFuncSetAttribute(klg, cudaFuncAttributeMaxDynamicSharedMemorySize, (int)smem_sz);

    static cudaStream_t s2 = nullptr;
    static cudaEvent_t evF = nullptr, evA0 = nullptr, evA1 = nullptr, evB = nullptr;
    if (!s2) {
        cudaStreamCreateWithFlags(&s2, cudaStreamNonBlocking);
        cudaEventCreateWithFlags(&evF,  cudaEventDisableTiming);
        cudaEventCreateWithFlags(&evA0, cudaEventDisableTiming);
        cudaEventCreateWithFlags(&evA1, cudaEventDisableTiming);
        cudaEventCreateWithFlags(&evB,  cudaEventDisableTiming);
    }

    dim3 tb(32, 8);
    cudaEventRecord(evF, 0);
    cudaStreamWaitEvent(s2, evF, 0);

    // side stream: QKV weights for layer 0 first (gates layer-0 start)
    transpose_cvt<<<dim3(32, 32, 1), tb, 0, s2>>>(wq, wqT, D_, D_);
    transpose_cvt<<<dim3(32, 32, 1), tb, 0, s2>>>(wk, wkT, D_, D_);
    transpose_cvt<<<dim3(32, 32, 1), tb, 0, s2>>>(wv, wvT, D_, D_);
    cudaEventRecord(evA0, s2);

    // layer-0 WO/W1/W2 (complete under layer-0 QKV + attention)
    transpose_cvt<<<dim3(32, 32, 1), tb, 0, s2>>>(wo, woT, D_, D_);
    transpose_cvt<<<dim3(DFF_ / 32, D_ / 32, 1), tb, 0, s2>>>(w1, w1T, D_, DFF_);
    transpose_cvt<<<dim3(D_ / 32, DFF_ / 32, 1), tb, 0, s2>>>(w2, w2T, DFF_, D_);
    cudaEventRecord(evA1, s2);

    // layers 1..3 + te cast
    transpose_cvt<<<dim3(32, 32, L_ - 1), tb, 0, s2>>>(wq + (size_t)D_ * D_, wqT + (size_t)D_ * D_, D_, D_);
    transpose_cvt<<<dim3(32, 32, L_ - 1), tb, 0, s2>>>(wk + (size_t)D_ * D_, wkT + (size_t)D_ * D_, D_, D_);
    transpose_cvt<<<dim3(32, 32, L_ - 1), tb, 0, s2>>>(wv + (size_t)D_ * D_, wvT + (size_t)D_ * D_, D_, D_);
    transpose_cvt<<<dim3(32, 32, L_ - 1), tb, 0, s2>>>(wo + (size_t)D_ * D_, woT + (size_t)D_ * D_, D_, D_);
    transpose_cvt<<<dim3(DFF_ / 32, D_ / 32, L_ - 1), tb, 0, s2>>>(w1 + (size_t)D_ * DFF_, w1T + (size_t)D_ * DFF_, D_, DFF_);
    transpose_cvt<<<dim3(D_ / 32, DFF_ / 32, L_ - 1), tb, 0, s2>>>(w2 + (size_t)DFF_ * D_, w2T + (size_t)DFF_ * D_, DFF_, D_);
    {
        long long nte = (long long)V_ * D_;
        int gte = (int)((nte + 2047) / 2048);
        cvt_f16_kernel<<<gte, 256, 0, s2>>>(te, teh, nte);
    }
    cudaEventRecord(evB, s2);

    embed_kernel<<<NTOK, 256>>>(idx, te, pe, x, xr);

    const dim3 gQKV(D_ / 128, NTOK / 128, 3);
    const dim3 gSK (D_ / 128, NTOK / 128, 2);
    const dim3 gF  (DFF_ / 128, NTOK / 128);
    const dim3 gFA (S_ / 128, B_ * H_);
    const dim3 gLg (NTOK / 128, (V_ + 127) / 128);
    const int NN = NTOK * D_;

    for (int l = 0; l < L_; l++) {
        if (l == 1) cudaStreamWaitEvent(0, evB, 0);

        const __half* wq_l = wqT + (size_t)l * D_ * D_;
        const __half* wk_l = wkT + (size_t)l * D_ * D_;
        const __half* wv_l = wvT + (size_t)l * D_ * D_;
        const __half* wo_l = woT + (size_t)l * D_ * D_;
        const __half* w1_l = w1T + (size_t)l * D_ * DFF_;
        const __half* w2_l = w2T + (size_t)l * DFF_ * D_;

        if (l == 0) cudaStreamWaitEvent(0, evA0, 0);
        kq<<<gQKV, 256, smem_sz>>>(
            xr, wq_l, bq + l * D_, q, NTOK, D_, D_, D_, D_, D_,
            wk_l, bk + l * D_, k, wv_l, bv + l * D_, v);

        flash_attn<<<gFA, 256>>>(q, k, v, y);

        if (l == 0) cudaStreamWaitEvent(0, evA1, 0);
        ksk<<<gSK, 256, smem_sz>>>(
            y, wo_l, nullptr, p, NTOK, D_, D_, D_, D_, D_,
            nullptr, nullptr, nullptr, nullptr, nullptr, nullptr);
        reduce_ln_kernel<<<NTOK, 256>>>(p, bo + l * D_, x, xr,
                                        ln2g + l * D_, ln2b + l * D_, ln, NN);

        kw1<<<gF, 256, smem_sz>>>(
            ln, w1_l, b1 + l * DFF_, h1, NTOK, DFF_, D_, D_, D_, DFF_,
            nullptr, nullptr, nullptr, nullptr, nullptr, nullptr);

        ksk<<<gSK, 256, smem_sz>>>(
            h1, w2_l, nullptr, p, NTOK, D_, DFF_, DFF_, DFF_, D_,
            nullptr, nullptr, nullptr, nullptr, nullptr, nullptr);
        if (l < L_ - 1) {
            reduce_splitk<<<NN / 1024, 256>>>(p, b2 + l * D_, x, xr, NN, D_);
        } else {
            reduce_ln_kernel<<<NTOK, 256>>>(p, b2 + l * D_, x, xr,
                                            lnfg, lnfb, ln, NN);
        }
    }

    // logits = lnf(x) @ te^T  (m fastest: te L2 reuse)
    klg<<<gLg, 256, smem_sz>>>(
        ln, teh, nullptr, out, NTOK, V_, D_, D_, D_, V_,
        nullptr, nullptr, nullptr, nullptr, nullptr, nullptr);
}